// round 7
// baseline (speedup 1.0000x reference)
#include <cuda_runtime.h>
#include <cuda_bf16.h>
#include <math.h>

#define NN 20000
#define HID 128
#define GB 157          // GEMM blocks for 20000 rows @128/tile

// ---------------- single scratch buffer ----------------
#define OFF_H     0
#define OFF_M     2560000
#define OFF_SKIP  5120000
#define OFF_AGG   7680000
#define OFF_S1    10240000   // contiguous after agg: agg | s1 | s2
#define OFF_S2    10260000
#define OFF_DEG1  10280000   // contiguous: deg1 | deg2
#define OFF_DEG2  10300000
#define SCRATCH_F 10320000
__device__ float g_scratch[SCRATCH_F];

// ---------------- helpers ----------------
__global__ void zero4_kernel(float4* __restrict__ p, int n4) {
    int i = blockIdx.x * blockDim.x + threadIdx.x;
    if (i < n4) p[i] = make_float4(0.f, 0.f, 0.f, 0.f);
}

// agg <- broadcast bias ; s1|s2 <- 0   (agg|s1|s2 contiguous)
__global__ void init_agg(float4* __restrict__ agg4, const float4* __restrict__ bias4) {
    int i = blockIdx.x * blockDim.x + threadIdx.x;
    const int NA = NN * HID / 4;
    if (i < NA) agg4[i] = bias4[i & 31];
    else if (i < NA + 2 * NN / 4) agg4[i] = make_float4(0.f, 0.f, 0.f, 0.f);
}

// fused warp-aggregated degree count for both edge lists (deg2 = deg + NN)
__global__ void count_deg_both(const int* __restrict__ row1, int E1,
                               const int* __restrict__ row2, int E2,
                               float* __restrict__ deg) {
    int e = blockIdx.x * blockDim.x + threadIdx.x;
    if (e >= E1 + E2) return;
    int key = (e < E1) ? row1[e] : (NN + row2[e - E1]);
    unsigned m = __match_any_sync(__activemask(), key);
    if ((threadIdx.x & 31) == (__ffs(m) - 1)) atomicAdd(&deg[key], (float)__popc(m));
}

__device__ __forceinline__ unsigned f2tf32(float x) {
    unsigned r;
    asm("cvt.rna.tf32.f32 %0, %1;" : "=r"(r) : "f"(x));
    return r;
}

__device__ __forceinline__ float warp_red(float s) {
#pragma unroll
    for (int off = 16; off; off >>= 1) s += __shfl_xor_sync(0xffffffffu, s, off);
    return s;
}

__device__ __forceinline__ float4 relu4(float4 v) {
    return make_float4(fmaxf(v.x, 0.f), fmaxf(v.y, 0.f), fmaxf(v.z, 0.f), fmaxf(v.w, 0.f));
}

// ---------------- split-TF32 tensor GEMM (templated variants) ----------------
// MODE 0: C = A @ W
// MODE 1: dual — blocks [0,GB): C=A@W ; [GB,2GB): C2=A2@W   (shared W)
// MODE 2: fused h-update: Aupd = (A + g1*relu(agg) + g2*skip)/(1+g1+g2),
//         writes Aupd back to hout and computes C = Aupd @ W
//
// W fragments are pre-packed per (lane, ki, nt): identical for all warps.
//   Wv[lane*68 + ki*16 + nt] = W[k = ki*4 + (lane&3)][c = nt*8 + (lane>>2)]
// Consumer reads them as uint4 (conflict-free: lane stride 68 words -> 4-bank groups).
#define KCH 16
#define SPAD 136
#define WLS 68   // per-lane W-frag stride in words (64 used + 4 pad)
template<int MODE>
__global__ __launch_bounds__(256) void gemm_k(
    const float* A, const float* __restrict__ A2,
    const float* __restrict__ W, float* __restrict__ C, float* __restrict__ C2,
    const float* __restrict__ agg, const float* __restrict__ skip,
    const float* __restrict__ s1, const float* __restrict__ s2,
    const float* __restrict__ deg1, const float* __restrict__ deg2,
    float* hout, int N) {
    __shared__ unsigned As_hi[KCH * SPAD], As_lo[KCH * SPAD];
    __shared__ unsigned Wv_hi[32 * WLS], Wv_lo[32 * WLS];
    __shared__ float cg1[128], cg2[128], cid[128];

    const int tid = threadIdx.x;
    const int lane = tid & 31;
    const int warp = tid >> 5;
    const int g = lane >> 2;
    const int t = lane & 3;
    const int mbase = warp * 16;

    const float* Ap = A;
    float* Cp = C;
    int rowBase;
    if (MODE == 1) {
        if (blockIdx.x < GB) rowBase = blockIdx.x * 128;
        else { Ap = A2; Cp = C2; rowBase = (blockIdx.x - GB) * 128; }
    } else {
        rowBase = blockIdx.x * 128;
    }

    if (MODE == 2) {
        if (tid < 128) {
            int r = rowBase + tid;
            float G1 = 0.f, G2 = 0.f, ID = 1.f;
            if (r < N) {
                G1 = tanhf(s1[r] / (deg1[r] + 1e-10f));
                G2 = tanhf(s2[r] / (deg2[r] + 1e-10f));
                ID = 1.0f / (1.0f + G1 + G2);
            }
            cg1[tid] = G1; cg2[tid] = G2; cid[tid] = ID;
        }
        __syncthreads();
    }

    float acc[16][4];
#pragma unroll
    for (int n = 0; n < 16; n++)
#pragma unroll
        for (int j = 0; j < 4; j++) acc[n][j] = 0.0f;

    float4 pa[2], pw[2];

    // ---- global prefetch (A with optional fused h-update; W rows) ----
    auto loadA = [&](int k0) {
#pragma unroll
        for (int tt = 0; tt < 2; tt++) {
            int idx = tid + tt * 256;
            int r = idx >> 2;
            int kq = (idx & 3) * 4;
            float4 v = make_float4(0.f, 0.f, 0.f, 0.f);
            if (rowBase + r < N) {
                size_t off = (size_t)(rowBase + r) * HID + k0 + kq;
                if (MODE == 2) {
                    float4 h4 = *reinterpret_cast<const float4*>(&Ap[off]);
                    float4 a4 = relu4(*reinterpret_cast<const float4*>(&agg[off]));
                    float4 k4 = *reinterpret_cast<const float4*>(&skip[off]);
                    float G1 = cg1[r], G2 = cg2[r], ID = cid[r];
                    v.x = (h4.x + G1 * a4.x + G2 * k4.x) * ID;
                    v.y = (h4.y + G1 * a4.y + G2 * k4.y) * ID;
                    v.z = (h4.z + G1 * a4.z + G2 * k4.z) * ID;
                    v.w = (h4.w + G1 * a4.w + G2 * k4.w) * ID;
                    *reinterpret_cast<float4*>(&hout[off]) = v;
                } else {
                    v = *reinterpret_cast<const float4*>(&Ap[off]);
                }
            }
            pa[tt] = v;
        }
    };
    auto loadW = [&](int k0) {
#pragma unroll
        for (int tt = 0; tt < 2; tt++) {
            int idx = tid + tt * 256;
            int kr = idx >> 5;
            int nq = (idx & 31) * 4;
            pw[tt] = *reinterpret_cast<const float4*>(&W[(size_t)(k0 + kr) * HID + nq]);
        }
    };

    loadA(0); loadW(0);

    for (int k0 = 0; k0 < HID; k0 += KCH) {
        // ---- smem fill (with on-the-fly tf32 split) ----
#pragma unroll
        for (int tt = 0; tt < 2; tt++) {
            int idx = tid + tt * 256;
            int r = idx >> 2;
            int kq = (idx & 3) * 4;
            float f[4] = {pa[tt].x, pa[tt].y, pa[tt].z, pa[tt].w};
#pragma unroll
            for (int j = 0; j < 4; j++) {
                unsigned hi = f2tf32(f[j]);
                float lo = f[j] - __uint_as_float(hi);
                As_hi[(kq + j) * SPAD + r] = hi;
                As_lo[(kq + j) * SPAD + r] = f2tf32(lo);
            }
        }
#pragma unroll
        for (int tt = 0; tt < 2; tt++) {
            int idx = tid + tt * 256;
            int kr = idx >> 5;
            int nq = (idx & 31) * 4;
            float f[4] = {pw[tt].x, pw[tt].y, pw[tt].z, pw[tt].w};
#pragma unroll
            for (int j = 0; j < 4; j++) {
                int c = nq + j;
                int addr = ((c & 7) * 4 + (kr & 3)) * WLS + (kr >> 2) * 16 + (c >> 3);
                unsigned hi = f2tf32(f[j]);
                float lo = f[j] - __uint_as_float(hi);
                Wv_hi[addr] = hi;
                Wv_lo[addr] = f2tf32(lo);
            }
        }
        __syncthreads();

        // prefetch next chunk (overlaps with MMA block below)
        if (k0 + KCH < HID) { loadA(k0 + KCH); loadW(k0 + KCH); }

        const uint4* W4h = reinterpret_cast<const uint4*>(Wv_hi) + lane * (WLS / 4);
        const uint4* W4l = reinterpret_cast<const uint4*>(Wv_lo) + lane * (WLS / 4);

#pragma unroll
        for (int ks = 0; ks < 2; ks++) {
            int kb = ks * 8;
            int kia = kb >> 2;          // row kb+t
            int kib = kia + 1;          // row kb+t+4
            unsigned ah[4], al[4];
            ah[0] = As_hi[(kb + t) * SPAD + mbase + g];
            ah[1] = As_hi[(kb + t) * SPAD + mbase + g + 8];
            ah[2] = As_hi[(kb + t + 4) * SPAD + mbase + g];
            ah[3] = As_hi[(kb + t + 4) * SPAD + mbase + g + 8];
            al[0] = As_lo[(kb + t) * SPAD + mbase + g];
            al[1] = As_lo[(kb + t) * SPAD + mbase + g + 8];
            al[2] = As_lo[(kb + t + 4) * SPAD + mbase + g];
            al[3] = As_lo[(kb + t + 4) * SPAD + mbase + g + 8];
#pragma unroll
            for (int nt4 = 0; nt4 < 4; nt4++) {
                uint4 bha = W4h[kia * 4 + nt4];
                uint4 bhb = W4h[kib * 4 + nt4];
                uint4 bla = W4l[kia * 4 + nt4];
                uint4 blb = W4l[kib * 4 + nt4];
                const unsigned* pbha = reinterpret_cast<const unsigned*>(&bha);
                const unsigned* pbhb = reinterpret_cast<const unsigned*>(&bhb);
                const unsigned* pbla = reinterpret_cast<const unsigned*>(&bla);
                const unsigned* pblb = reinterpret_cast<const unsigned*>(&blb);
#pragma unroll
                for (int j = 0; j < 4; j++) {
                    int nt = nt4 * 4 + j;
                    unsigned bh0 = pbha[j], bh1 = pbhb[j];
                    unsigned bl0 = pbla[j], bl1 = pblb[j];
                    asm volatile("mma.sync.aligned.m16n8k8.row.col.f32.tf32.tf32.f32 "
                                 "{%0,%1,%2,%3}, {%4,%5,%6,%7}, {%8,%9}, {%0,%1,%2,%3};"
                                 : "+f"(acc[nt][0]), "+f"(acc[nt][1]), "+f"(acc[nt][2]), "+f"(acc[nt][3])
                                 : "r"(ah[0]), "r"(ah[1]), "r"(ah[2]), "r"(ah[3]), "r"(bh0), "r"(bh1));
                    asm volatile("mma.sync.aligned.m16n8k8.row.col.f32.tf32.tf32.f32 "
                                 "{%0,%1,%2,%3}, {%4,%5,%6,%7}, {%8,%9}, {%0,%1,%2,%3};"
                                 : "+f"(acc[nt][0]), "+f"(acc[nt][1]), "+f"(acc[nt][2]), "+f"(acc[nt][3])
                                 : "r"(ah[0]), "r"(ah[1]), "r"(ah[2]), "r"(ah[3]), "r"(bl0), "r"(bl1));
                    asm volatile("mma.sync.aligned.m16n8k8.row.col.f32.tf32.tf32.f32 "
                                 "{%0,%1,%2,%3}, {%4,%5,%6,%7}, {%8,%9}, {%0,%1,%2,%3};"
                                 : "+f"(acc[nt][0]), "+f"(acc[nt][1]), "+f"(acc[nt][2]), "+f"(acc[nt][3])
                                 : "r"(al[0]), "r"(al[1]), "r"(al[2]), "r"(al[3]), "r"(bh0), "r"(bh1));
                }
            }
        }
        __syncthreads();
    }

    int r0 = rowBase + mbase + g;
    int r1 = r0 + 8;
    if (r0 < N) {
#pragma unroll
        for (int nt = 0; nt < 16; nt++)
            *reinterpret_cast<float2*>(&Cp[(size_t)r0 * HID + nt * 8 + 2 * t]) =
                make_float2(acc[nt][0], acc[nt][1]);
    }
    if (r1 < N) {
#pragma unroll
        for (int nt = 0; nt < 16; nt++)
            *reinterpret_cast<float2*>(&Cp[(size_t)r1 * HID + nt * 8 + 2 * t]) =
                make_float2(acc[nt][2], acc[nt][3]);
    }
}

// ---------------- scatter: agg[col[e]] += m[row[e]] ----------------
__global__ void scatter_add(const float* __restrict__ m, const int* __restrict__ row,
                            const int* __restrict__ col, float* __restrict__ agg, int E) {
    int w = (blockIdx.x * blockDim.x + threadIdx.x) >> 5;
    if (w >= E) return;
    int lane = threadIdx.x & 31;
    int r = row[w];
    int c = col[w];
    float4 v = *reinterpret_cast<const float4*>(&m[(size_t)r * HID + lane * 4]);
    float* dst = &agg[(size_t)c * HID + lane * 4];
    asm volatile("red.global.add.v4.f32 [%0], {%1, %2, %3, %4};"
                 :: "l"(dst), "f"(v.x), "f"(v.y), "f"(v.z), "f"(v.w) : "memory");
}

// ---------------- fused gamma over both edge lists (relu applied on load) ----------------
#define G2_CHUNK 64
__global__ void gamma_both(const float* __restrict__ agg,
                           const int* __restrict__ row1, const int* __restrict__ col1,
                           float* __restrict__ s1, int E1, int blocks1,
                           const int* __restrict__ row2, const int* __restrict__ col2,
                           float* __restrict__ s2, int E2) {
    int lane = threadIdx.x & 31;
    if (blockIdx.x < blocks1) {
        int w = (blockIdx.x * blockDim.x + threadIdx.x) >> 5;
        if (w >= E1) return;
        int r = row1[w];
        int c = col1[w];
        float4 a = relu4(*reinterpret_cast<const float4*>(&agg[(size_t)r * HID + lane * 4]));
        float4 b = relu4(*reinterpret_cast<const float4*>(&agg[(size_t)c * HID + lane * 4]));
        float dx = a.x - b.x, dy = a.y - b.y, dz = a.z - b.z, dw = a.w - b.w;
        float s = warp_red(fmaf(dx, dx, fmaf(dy, dy, fmaf(dz, dz, dw * dw))));
        if (lane == 0) atomicAdd(&s1[r], s);
    } else {
        int w = (int)((((size_t)(blockIdx.x - blocks1) * blockDim.x) + threadIdx.x) >> 5);
        int base = w * G2_CHUNK;
        if (base >= E2) return;
        int end = min(base + G2_CHUNK, E2);
        int curR = row2[base];
        float4 ar = relu4(*reinterpret_cast<const float4*>(&agg[(size_t)curR * HID + lane * 4]));
        float acc = 0.0f;
        for (int e = base; e < end; e++) {
            int r = row2[e];
            if (r != curR) {
                float s = warp_red(acc);
                if (lane == 0) atomicAdd(&s2[curR], s);
                acc = 0.0f;
                curR = r;
                ar = relu4(*reinterpret_cast<const float4*>(&agg[(size_t)r * HID + lane * 4]));
            }
            int c = col2[e];
            float4 ac = relu4(*reinterpret_cast<const float4*>(&agg[(size_t)c * HID + lane * 4]));
            float dx = ar.x - ac.x, dy = ar.y - ac.y, dz = ar.z - ac.z, dw = ar.w - ac.w;
            acc += fmaf(dx, dx, fmaf(dy, dy, fmaf(dz, dz, dw * dw)));
        }
        float s = warp_red(acc);
        if (lane == 0) atomicAdd(&s2[curR], s);
    }
}

// ---------------- final GEMM with fused layer-2 h-update: out = h_upd @ fc_W + fc_b ----------------
#define ORPB 16
__global__ __launch_bounds__(640) void gemm_out_upd(
    const float* __restrict__ h, const float* __restrict__ agg, const float* __restrict__ skip,
    const float* __restrict__ s1, const float* __restrict__ s2,
    const float* __restrict__ deg1, const float* __restrict__ deg2,
    const float* __restrict__ W, const float* __restrict__ bias,
    float* __restrict__ C, int N) {
    __shared__ float Ws[HID * 41];
    __shared__ float bs[40];
    __shared__ float As[ORPB][HID];
    __shared__ float cg1[ORPB], cg2[ORPB], cid[ORPB];
    int tid = threadIdx.y * 40 + threadIdx.x;
    int rowBase = blockIdx.x * ORPB;

    for (int i = tid; i < HID * 40; i += 640) {
        int k = i / 40, n = i % 40;
        Ws[k * 41 + n] = W[i];
    }
    if (tid < 40) bs[tid] = bias[tid];
    if (tid < ORPB) {
        int r = rowBase + tid;
        float g1 = 0.f, g2 = 0.f, invd = 1.f;
        if (r < N) {
            g1 = tanhf(s1[r] / (deg1[r] + 1e-10f));
            g2 = tanhf(s2[r] / (deg2[r] + 1e-10f));
            invd = 1.0f / (1.0f + g1 + g2);
        }
        cg1[tid] = g1; cg2[tid] = g2; cid[tid] = invd;
    }
    __syncthreads();

    for (int i = tid; i < ORPB * HID; i += 640) {
        int rr = i >> 7, kk = i & (HID - 1);
        int r = rowBase + rr;
        float v = 0.0f;
        if (r < N) {
            size_t off = (size_t)r * HID + kk;
            v = (h[off] + cg1[rr] * fmaxf(agg[off], 0.f) + cg2[rr] * skip[off]) * cid[rr];
        }
        As[rr][kk] = v;
    }
    __syncthreads();

    int row = rowBase + threadIdx.y;
    if (row >= N) return;
    float acc = bs[threadIdx.x];
#pragma unroll
    for (int k = 0; k < HID; k++) acc = fmaf(As[threadIdx.y][k], Ws[k * 41 + threadIdx.x], acc);
    C[(size_t)row * 40 + threadIdx.x] = acc;
}

// ---------------- launcher ----------------
extern "C" void kernel_launch(void* const* d_in, const int* in_sizes, int n_in,
                              void* d_out, int out_size) {
    const float* x       = (const float*)d_in[0];
    const float* x0      = (const float*)d_in[1];
    const int*   ei      = (const int*)d_in[2];
    const int*   ei2     = (const int*)d_in[3];
    const float* in_W    = (const float*)d_in[4];
    const float* skip_W  = (const float*)d_in[5];
    const float* conv_W  = (const float*)d_in[6];
    const float* conv_b  = (const float*)d_in[7];
    const float* fc_W    = (const float*)d_in[8];
    const float* fc_b    = (const float*)d_in[9];
    float* out = (float*)d_out;

    const int E1 = in_sizes[2] / 2;
    const int E2 = in_sizes[3] / 2;
    const int* row1 = ei;
    const int* col1 = ei + E1;
    const int* row2 = ei2;
    const int* col2 = ei2 + E2;

    float* base;
    cudaGetSymbolAddress((void**)&base, g_scratch);
    float* h    = base + OFF_H;
    float* m    = base + OFF_M;
    float* skip = base + OFF_SKIP;
    float* agg  = base + OFF_AGG;
    float* s1   = base + OFF_S1;
    float* s2   = base + OFF_S2;
    float* deg1 = base + OFF_DEG1;
    float* deg2 = base + OFF_DEG2;

    const int NTH = 256;

    zero4_kernel<<<(2 * NN / 4 + NTH - 1) / NTH, NTH>>>((float4*)deg1, 2 * NN / 4);
    count_deg_both<<<(E1 + E2 + NTH - 1) / NTH, NTH>>>(row1, E1, row2, E2, deg1);

    // dual input projection: h = x@in_W, m(=h0) = x0@in_W (shared W)
    gemm_k<1><<<2 * GB, NTH>>>(x, x0, in_W, h, m,
                               nullptr, nullptr, nullptr, nullptr, nullptr, nullptr, nullptr, NN);
    // x_skip = h0 @ skip_W
    gemm_k<0><<<GB, NTH>>>(m, nullptr, skip_W, skip, nullptr,
                           nullptr, nullptr, nullptr, nullptr, nullptr, nullptr, nullptr, NN);

    const int initGrid = (NN * HID / 4 + 2 * NN / 4 + NTH - 1) / NTH;
    const int blocks1 = (int)(((size_t)E1 * 32 + NTH - 1) / NTH);
    const int warps2  = (E2 + G2_CHUNK - 1) / G2_CHUNK;
    const int blocks2 = (warps2 * 32 + NTH - 1) / NTH;

    // ---- layer 0 ----
    gemm_k<0><<<GB, NTH>>>(h, nullptr, conv_W, m, nullptr,
                           nullptr, nullptr, nullptr, nullptr, nullptr, nullptr, nullptr, NN);
    init_agg<<<initGrid, NTH>>>((float4*)agg, (const float4*)(conv_b));
    scatter_add<<<(int)(((size_t)E1 * 32 + NTH - 1) / NTH), NTH>>>(m, row1, col1, agg, E1);
    gamma_both<<<blocks1 + blocks2, NTH>>>(agg, row1, col1, s1, E1, blocks1, row2, col2, s2, E2);

    // ---- layer 1 (h-update fused into conv GEMM) ----
    gemm_k<2><<<GB, NTH>>>(h, nullptr, conv_W + (size_t)HID * HID, m, nullptr,
                           agg, skip, s1, s2, deg1, deg2, h, NN);
    init_agg<<<initGrid, NTH>>>((float4*)agg, (const float4*)(conv_b + HID));
    scatter_add<<<(int)(((size_t)E1 * 32 + NTH - 1) / NTH), NTH>>>(m, row1, col1, agg, E1);
    gamma_both<<<blocks1 + blocks2, NTH>>>(agg, row1, col1, s1, E1, blocks1, row2, col2, s2, E2);

    // ---- output (layer-2 h-update fused) ----
    gemm_out_upd<<<(NN + ORPB - 1) / ORPB, dim3(40, ORPB)>>>(
        h, agg, skip, s1, s2, deg1, deg2, fc_W, fc_b, out, NN);
}

// round 8
// speedup vs baseline: 1.0422x; 1.0422x over previous
#include <cuda_runtime.h>
#include <cuda_bf16.h>
#include <math.h>

#define NN 20000
#define HID 128
#define GB 157          // GEMM blocks for 20000 rows @128/tile

// ---------------- single scratch buffer ----------------
#define OFF_H     0
#define OFF_M     2560000
#define OFF_SKIP  5120000
#define OFF_AGG   7680000
#define OFF_S1    10240000   // contiguous after agg: agg | s1 | s2
#define OFF_S2    10260000
#define OFF_DEG1  10280000   // contiguous: deg1 | deg2
#define OFF_DEG2  10300000
#define SCRATCH_F 10320000
__device__ float g_scratch[SCRATCH_F];

// ---------------- helpers ----------------
__global__ void zero4_kernel(float4* __restrict__ p, int n4) {
    int i = blockIdx.x * blockDim.x + threadIdx.x;
    if (i < n4) p[i] = make_float4(0.f, 0.f, 0.f, 0.f);
}

// agg <- broadcast bias ; s1|s2 <- 0   (agg|s1|s2 contiguous)
__global__ void init_agg(float4* __restrict__ agg4, const float4* __restrict__ bias4) {
    int i = blockIdx.x * blockDim.x + threadIdx.x;
    const int NA = NN * HID / 4;
    if (i < NA) agg4[i] = bias4[i & 31];
    else if (i < NA + 2 * NN / 4) agg4[i] = make_float4(0.f, 0.f, 0.f, 0.f);
}

// fused warp-aggregated degree count for both edge lists (deg2 = deg + NN)
__global__ void count_deg_both(const int* __restrict__ row1, int E1,
                               const int* __restrict__ row2, int E2,
                               float* __restrict__ deg) {
    int e = blockIdx.x * blockDim.x + threadIdx.x;
    if (e >= E1 + E2) return;
    int key = (e < E1) ? row1[e] : (NN + row2[e - E1]);
    unsigned m = __match_any_sync(__activemask(), key);
    if ((threadIdx.x & 31) == (__ffs(m) - 1)) atomicAdd(&deg[key], (float)__popc(m));
}

__device__ __forceinline__ unsigned f2tf32(float x) {
    unsigned r;
    asm("cvt.rna.tf32.f32 %0, %1;" : "=r"(r) : "f"(x));
    return r;
}

__device__ __forceinline__ float warp_red(float s) {
#pragma unroll
    for (int off = 16; off; off >>= 1) s += __shfl_xor_sync(0xffffffffu, s, off);
    return s;
}

__device__ __forceinline__ float4 relu4(float4 v) {
    return make_float4(fmaxf(v.x, 0.f), fmaxf(v.y, 0.f), fmaxf(v.z, 0.f), fmaxf(v.w, 0.f));
}

// ---------------- split-TF32 tensor GEMM (templated variants) ----------------
// MODE 0: C = A @ W
// MODE 1: dual — blocks [0,GB): C=A@W ; [GB,2GB): C2=A2@W   (shared W)
// MODE 2: fused h-update: Aupd = (A + g1*relu(agg) + g2*skip)/(1+g1+g2),
//         writes Aupd back to hout and computes C = Aupd @ W
// __launch_bounds__(256, 2): 2 CTAs/SM -> one wave for grid<=296, cross-CTA phase overlap.
#define KCH 16
#define SPAD 136
#define WLS 68   // per-lane W-frag stride in words (64 used + 4 pad)
template<int MODE>
__global__ __launch_bounds__(256, 2) void gemm_k(
    const float* A, const float* __restrict__ A2,
    const float* __restrict__ W, float* __restrict__ C, float* __restrict__ C2,
    const float* __restrict__ agg, const float* __restrict__ skip,
    const float* __restrict__ s1, const float* __restrict__ s2,
    const float* __restrict__ deg1, const float* __restrict__ deg2,
    float* hout, int N) {
    __shared__ unsigned As_hi[KCH * SPAD], As_lo[KCH * SPAD];
    __shared__ unsigned Wv_hi[32 * WLS], Wv_lo[32 * WLS];
    __shared__ float cg1[128], cg2[128], cid[128];

    const int tid = threadIdx.x;
    const int lane = tid & 31;
    const int warp = tid >> 5;
    const int g = lane >> 2;
    const int t = lane & 3;
    const int mbase = warp * 16;

    const float* Ap = A;
    float* Cp = C;
    int rowBase;
    if (MODE == 1) {
        if (blockIdx.x < GB) rowBase = blockIdx.x * 128;
        else { Ap = A2; Cp = C2; rowBase = (blockIdx.x - GB) * 128; }
    } else {
        rowBase = blockIdx.x * 128;
    }

    if (MODE == 2) {
        if (tid < 128) {
            int r = rowBase + tid;
            float G1 = 0.f, G2 = 0.f, ID = 1.f;
            if (r < N) {
                G1 = tanhf(s1[r] / (deg1[r] + 1e-10f));
                G2 = tanhf(s2[r] / (deg2[r] + 1e-10f));
                ID = 1.0f / (1.0f + G1 + G2);
            }
            cg1[tid] = G1; cg2[tid] = G2; cid[tid] = ID;
        }
        __syncthreads();
    }

    float acc[16][4];
#pragma unroll
    for (int n = 0; n < 16; n++)
#pragma unroll
        for (int j = 0; j < 4; j++) acc[n][j] = 0.0f;

    float4 pa[2], pw[2];

    auto loadA = [&](int k0) {
#pragma unroll
        for (int tt = 0; tt < 2; tt++) {
            int idx = tid + tt * 256;
            int r = idx >> 2;
            int kq = (idx & 3) * 4;
            float4 v = make_float4(0.f, 0.f, 0.f, 0.f);
            if (rowBase + r < N) {
                size_t off = (size_t)(rowBase + r) * HID + k0 + kq;
                if (MODE == 2) {
                    float4 h4 = *reinterpret_cast<const float4*>(&Ap[off]);
                    float4 a4 = relu4(*reinterpret_cast<const float4*>(&agg[off]));
                    float4 k4 = *reinterpret_cast<const float4*>(&skip[off]);
                    float G1 = cg1[r], G2 = cg2[r], ID = cid[r];
                    v.x = (h4.x + G1 * a4.x + G2 * k4.x) * ID;
                    v.y = (h4.y + G1 * a4.y + G2 * k4.y) * ID;
                    v.z = (h4.z + G1 * a4.z + G2 * k4.z) * ID;
                    v.w = (h4.w + G1 * a4.w + G2 * k4.w) * ID;
                    *reinterpret_cast<float4*>(&hout[off]) = v;
                } else {
                    v = *reinterpret_cast<const float4*>(&Ap[off]);
                }
            }
            pa[tt] = v;
        }
    };
    auto loadW = [&](int k0) {
#pragma unroll
        for (int tt = 0; tt < 2; tt++) {
            int idx = tid + tt * 256;
            int kr = idx >> 5;
            int nq = (idx & 31) * 4;
            pw[tt] = *reinterpret_cast<const float4*>(&W[(size_t)(k0 + kr) * HID + nq]);
        }
    };

    loadA(0); loadW(0);

    for (int k0 = 0; k0 < HID; k0 += KCH) {
        // ---- smem fill (with on-the-fly tf32 split) ----
#pragma unroll
        for (int tt = 0; tt < 2; tt++) {
            int idx = tid + tt * 256;
            int r = idx >> 2;
            int kq = (idx & 3) * 4;
            float f[4] = {pa[tt].x, pa[tt].y, pa[tt].z, pa[tt].w};
#pragma unroll
            for (int j = 0; j < 4; j++) {
                unsigned hi = f2tf32(f[j]);
                float lo = f[j] - __uint_as_float(hi);
                As_hi[(kq + j) * SPAD + r] = hi;
                As_lo[(kq + j) * SPAD + r] = f2tf32(lo);
            }
        }
#pragma unroll
        for (int tt = 0; tt < 2; tt++) {
            int idx = tid + tt * 256;
            int kr = idx >> 5;
            int nq = (idx & 31) * 4;
            float f[4] = {pw[tt].x, pw[tt].y, pw[tt].z, pw[tt].w};
#pragma unroll
            for (int j = 0; j < 4; j++) {
                int c = nq + j;
                int addr = ((c & 7) * 4 + (kr & 3)) * WLS + (kr >> 2) * 16 + (c >> 3);
                unsigned hi = f2tf32(f[j]);
                float lo = f[j] - __uint_as_float(hi);
                Wv_hi[addr] = hi;
                Wv_lo[addr] = f2tf32(lo);
            }
        }
        __syncthreads();

        // prefetch next chunk (overlaps with MMA block below)
        if (k0 + KCH < HID) { loadA(k0 + KCH); loadW(k0 + KCH); }

        const uint4* W4h = reinterpret_cast<const uint4*>(Wv_hi) + lane * (WLS / 4);
        const uint4* W4l = reinterpret_cast<const uint4*>(Wv_lo) + lane * (WLS / 4);

#pragma unroll
        for (int ks = 0; ks < 2; ks++) {
            int kb = ks * 8;
            int kia = kb >> 2;
            int kib = kia + 1;
            unsigned ah[4], al[4];
            ah[0] = As_hi[(kb + t) * SPAD + mbase + g];
            ah[1] = As_hi[(kb + t) * SPAD + mbase + g + 8];
            ah[2] = As_hi[(kb + t + 4) * SPAD + mbase + g];
            ah[3] = As_hi[(kb + t + 4) * SPAD + mbase + g + 8];
            al[0] = As_lo[(kb + t) * SPAD + mbase + g];
            al[1] = As_lo[(kb + t) * SPAD + mbase + g + 8];
            al[2] = As_lo[(kb + t + 4) * SPAD + mbase + g];
            al[3] = As_lo[(kb + t + 4) * SPAD + mbase + g + 8];
#pragma unroll
            for (int nt4 = 0; nt4 < 4; nt4++) {
                uint4 bha = W4h[kia * 4 + nt4];
                uint4 bhb = W4h[kib * 4 + nt4];
                uint4 bla = W4l[kia * 4 + nt4];
                uint4 blb = W4l[kib * 4 + nt4];
                const unsigned* pbha = reinterpret_cast<const unsigned*>(&bha);
                const unsigned* pbhb = reinterpret_cast<const unsigned*>(&bhb);
                const unsigned* pbla = reinterpret_cast<const unsigned*>(&bla);
                const unsigned* pblb = reinterpret_cast<const unsigned*>(&blb);
#pragma unroll
                for (int j = 0; j < 4; j++) {
                    int nt = nt4 * 4 + j;
                    unsigned bh0 = pbha[j], bh1 = pbhb[j];
                    unsigned bl0 = pbla[j], bl1 = pblb[j];
                    asm volatile("mma.sync.aligned.m16n8k8.row.col.f32.tf32.tf32.f32 "
                                 "{%0,%1,%2,%3}, {%4,%5,%6,%7}, {%8,%9}, {%0,%1,%2,%3};"
                                 : "+f"(acc[nt][0]), "+f"(acc[nt][1]), "+f"(acc[nt][2]), "+f"(acc[nt][3])
                                 : "r"(ah[0]), "r"(ah[1]), "r"(ah[2]), "r"(ah[3]), "r"(bh0), "r"(bh1));
                    asm volatile("mma.sync.aligned.m16n8k8.row.col.f32.tf32.tf32.f32 "
                                 "{%0,%1,%2,%3}, {%4,%5,%6,%7}, {%8,%9}, {%0,%1,%2,%3};"
                                 : "+f"(acc[nt][0]), "+f"(acc[nt][1]), "+f"(acc[nt][2]), "+f"(acc[nt][3])
                                 : "r"(ah[0]), "r"(ah[1]), "r"(ah[2]), "r"(ah[3]), "r"(bl0), "r"(bl1));
                    asm volatile("mma.sync.aligned.m16n8k8.row.col.f32.tf32.tf32.f32 "
                                 "{%0,%1,%2,%3}, {%4,%5,%6,%7}, {%8,%9}, {%0,%1,%2,%3};"
                                 : "+f"(acc[nt][0]), "+f"(acc[nt][1]), "+f"(acc[nt][2]), "+f"(acc[nt][3])
                                 : "r"(al[0]), "r"(al[1]), "r"(al[2]), "r"(al[3]), "r"(bh0), "r"(bh1));
                }
            }
        }
        __syncthreads();
    }

    int r0 = rowBase + mbase + g;
    int r1 = r0 + 8;
    if (r0 < N) {
#pragma unroll
        for (int nt = 0; nt < 16; nt++)
            *reinterpret_cast<float2*>(&Cp[(size_t)r0 * HID + nt * 8 + 2 * t]) =
                make_float2(acc[nt][0], acc[nt][1]);
    }
    if (r1 < N) {
#pragma unroll
        for (int nt = 0; nt < 16; nt++)
            *reinterpret_cast<float2*>(&Cp[(size_t)r1 * HID + nt * 8 + 2 * t]) =
                make_float2(acc[nt][2], acc[nt][3]);
    }
}

// ---------------- scatter: agg[col[e]] += m[row[e]] ----------------
__global__ void scatter_add(const float* __restrict__ m, const int* __restrict__ row,
                            const int* __restrict__ col, float* __restrict__ agg, int E) {
    int w = (blockIdx.x * blockDim.x + threadIdx.x) >> 5;
    if (w >= E) return;
    int lane = threadIdx.x & 31;
    int r = row[w];
    int c = col[w];
    float4 v = *reinterpret_cast<const float4*>(&m[(size_t)r * HID + lane * 4]);
    float* dst = &agg[(size_t)c * HID + lane * 4];
    asm volatile("red.global.add.v4.f32 [%0], {%1, %2, %3, %4};"
                 :: "l"(dst), "f"(v.x), "f"(v.y), "f"(v.z), "f"(v.w) : "memory");
}

// ---------------- fused gamma over both edge lists (relu applied on load) ----------------
#define G2_CHUNK 64
__global__ void gamma_both(const float* __restrict__ agg,
                           const int* __restrict__ row1, const int* __restrict__ col1,
                           float* __restrict__ s1, int E1, int blocks1,
                           const int* __restrict__ row2, const int* __restrict__ col2,
                           float* __restrict__ s2, int E2) {
    int lane = threadIdx.x & 31;
    if (blockIdx.x < blocks1) {
        int w = (blockIdx.x * blockDim.x + threadIdx.x) >> 5;
        if (w >= E1) return;
        int r = row1[w];
        int c = col1[w];
        float4 a = relu4(*reinterpret_cast<const float4*>(&agg[(size_t)r * HID + lane * 4]));
        float4 b = relu4(*reinterpret_cast<const float4*>(&agg[(size_t)c * HID + lane * 4]));
        float dx = a.x - b.x, dy = a.y - b.y, dz = a.z - b.z, dw = a.w - b.w;
        float s = warp_red(fmaf(dx, dx, fmaf(dy, dy, fmaf(dz, dz, dw * dw))));
        if (lane == 0) atomicAdd(&s1[r], s);
    } else {
        int w = (int)((((size_t)(blockIdx.x - blocks1) * blockDim.x) + threadIdx.x) >> 5);
        int base = w * G2_CHUNK;
        if (base >= E2) return;
        int end = min(base + G2_CHUNK, E2);
        int curR = row2[base];
        float4 ar = relu4(*reinterpret_cast<const float4*>(&agg[(size_t)curR * HID + lane * 4]));
        float acc = 0.0f;
        for (int e = base; e < end; e++) {
            int r = row2[e];
            if (r != curR) {
                float s = warp_red(acc);
                if (lane == 0) atomicAdd(&s2[curR], s);
                acc = 0.0f;
                curR = r;
                ar = relu4(*reinterpret_cast<const float4*>(&agg[(size_t)r * HID + lane * 4]));
            }
            int c = col2[e];
            float4 ac = relu4(*reinterpret_cast<const float4*>(&agg[(size_t)c * HID + lane * 4]));
            float dx = ar.x - ac.x, dy = ar.y - ac.y, dz = ar.z - ac.z, dw = ar.w - ac.w;
            acc += fmaf(dx, dx, fmaf(dy, dy, fmaf(dz, dz, dw * dw)));
        }
        float s = warp_red(acc);
        if (lane == 0) atomicAdd(&s2[curR], s);
    }
}

// ---------------- final GEMM with fused layer-2 h-update: out = h_upd @ fc_W + fc_b ----------------
#define ORPB 16
__global__ __launch_bounds__(640) void gemm_out_upd(
    const float* __restrict__ h, const float* __restrict__ agg, const float* __restrict__ skip,
    const float* __restrict__ s1, const float* __restrict__ s2,
    const float* __restrict__ deg1, const float* __restrict__ deg2,
    const float* __restrict__ W, const float* __restrict__ bias,
    float* __restrict__ C, int N) {
    __shared__ float Ws[HID * 41];
    __shared__ float bs[40];
    __shared__ float As[ORPB][HID];
    __shared__ float cg1[ORPB], cg2[ORPB], cid[ORPB];
    int tid = threadIdx.y * 40 + threadIdx.x;
    int rowBase = blockIdx.x * ORPB;

    for (int i = tid; i < HID * 40; i += 640) {
        int k = i / 40, n = i % 40;
        Ws[k * 41 + n] = W[i];
    }
    if (tid < 40) bs[tid] = bias[tid];
    if (tid < ORPB) {
        int r = rowBase + tid;
        float g1 = 0.f, g2 = 0.f, invd = 1.f;
        if (r < N) {
            g1 = tanhf(s1[r] / (deg1[r] + 1e-10f));
            g2 = tanhf(s2[r] / (deg2[r] + 1e-10f));
            invd = 1.0f / (1.0f + g1 + g2);
        }
        cg1[tid] = g1; cg2[tid] = g2; cid[tid] = invd;
    }
    __syncthreads();

    for (int i = tid; i < ORPB * HID; i += 640) {
        int rr = i >> 7, kk = i & (HID - 1);
        int r = rowBase + rr;
        float v = 0.0f;
        if (r < N) {
            size_t off = (size_t)r * HID + kk;
            v = (h[off] + cg1[rr] * fmaxf(agg[off], 0.f) + cg2[rr] * skip[off]) * cid[rr];
        }
        As[rr][kk] = v;
    }
    __syncthreads();

    int row = rowBase + threadIdx.y;
    if (row >= N) return;
    float acc = bs[threadIdx.x];
#pragma unroll
    for (int k = 0; k < HID; k++) acc = fmaf(As[threadIdx.y][k], Ws[k * 41 + threadIdx.x], acc);
    C[(size_t)row * 40 + threadIdx.x] = acc;
}

// ---------------- launcher ----------------
extern "C" void kernel_launch(void* const* d_in, const int* in_sizes, int n_in,
                              void* d_out, int out_size) {
    const float* x       = (const float*)d_in[0];
    const float* x0      = (const float*)d_in[1];
    const int*   ei      = (const int*)d_in[2];
    const int*   ei2     = (const int*)d_in[3];
    const float* in_W    = (const float*)d_in[4];
    const float* skip_W  = (const float*)d_in[5];
    const float* conv_W  = (const float*)d_in[6];
    const float* conv_b  = (const float*)d_in[7];
    const float* fc_W    = (const float*)d_in[8];
    const float* fc_b    = (const float*)d_in[9];
    float* out = (float*)d_out;

    const int E1 = in_sizes[2] / 2;
    const int E2 = in_sizes[3] / 2;
    const int* row1 = ei;
    const int* col1 = ei + E1;
    const int* row2 = ei2;
    const int* col2 = ei2 + E2;

    float* base;
    cudaGetSymbolAddress((void**)&base, g_scratch);
    float* h    = base + OFF_H;
    float* m    = base + OFF_M;
    float* skip = base + OFF_SKIP;
    float* agg  = base + OFF_AGG;
    float* s1   = base + OFF_S1;
    float* s2   = base + OFF_S2;
    float* deg1 = base + OFF_DEG1;
    float* deg2 = base + OFF_DEG2;

    const int NTH = 256;

    zero4_kernel<<<(2 * NN / 4 + NTH - 1) / NTH, NTH>>>((float4*)deg1, 2 * NN / 4);
    count_deg_both<<<(E1 + E2 + NTH - 1) / NTH, NTH>>>(row1, E1, row2, E2, deg1);

    // dual input projection: h = x@in_W, m(=h0) = x0@in_W (shared W)
    gemm_k<1><<<2 * GB, NTH>>>(x, x0, in_W, h, m,
                               nullptr, nullptr, nullptr, nullptr, nullptr, nullptr, nullptr, NN);
    // x_skip = h0 @ skip_W
    gemm_k<0><<<GB, NTH>>>(m, nullptr, skip_W, skip, nullptr,
                           nullptr, nullptr, nullptr, nullptr, nullptr, nullptr, nullptr, NN);

    const int initGrid = (NN * HID / 4 + 2 * NN / 4 + NTH - 1) / NTH;
    const int blocks1 = (int)(((size_t)E1 * 32 + NTH - 1) / NTH);
    const int warps2  = (E2 + G2_CHUNK - 1) / G2_CHUNK;
    const int blocks2 = (warps2 * 32 + NTH - 1) / NTH;

    // ---- layer 0 ----
    gemm_k<0><<<GB, NTH>>>(h, nullptr, conv_W, m, nullptr,
                           nullptr, nullptr, nullptr, nullptr, nullptr, nullptr, nullptr, NN);
    init_agg<<<initGrid, NTH>>>((float4*)agg, (const float4*)(conv_b));
    scatter_add<<<(int)(((size_t)E1 * 32 + NTH - 1) / NTH), NTH>>>(m, row1, col1, agg, E1);
    gamma_both<<<blocks1 + blocks2, NTH>>>(agg, row1, col1, s1, E1, blocks1, row2, col2, s2, E2);

    // ---- layer 1 (h-update fused into conv GEMM) ----
    gemm_k<2><<<GB, NTH>>>(h, nullptr, conv_W + (size_t)HID * HID, m, nullptr,
                           agg, skip, s1, s2, deg1, deg2, h, NN);
    init_agg<<<initGrid, NTH>>>((float4*)agg, (const float4*)(conv_b + HID));
    scatter_add<<<(int)(((size_t)E1 * 32 + NTH - 1) / NTH), NTH>>>(m, row1, col1, agg, E1);
    gamma_both<<<blocks1 + blocks2, NTH>>>(agg, row1, col1, s1, E1, blocks1, row2, col2, s2, E2);

    // ---- output (layer-2 h-update fused) ----
    gemm_out_upd<<<(NN + ORPB - 1) / ORPB, dim3(40, ORPB)>>>(
        h, agg, skip, s1, s2, deg1, deg2, fc_W, fc_b, out, NN);
}

// round 9
// speedup vs baseline: 1.2303x; 1.1804x over previous
#include <cuda_runtime.h>
#include <cuda_bf16.h>
#include <math.h>

#define NN 20000
#define HID 128
#define GB 157          // GEMM blocks for 20000 rows @128/tile

// ---------------- single scratch buffer ----------------
#define OFF_H     0
#define OFF_M     2560000
#define OFF_SKIP  5120000
#define OFF_AGG   7680000
#define OFF_S1    10240000   // contiguous after agg: agg | s1 | s2
#define OFF_S2    10260000
#define OFF_DEG1  10280000   // contiguous: deg1 | deg2
#define OFF_DEG2  10300000
#define SCRATCH_F 10320000
__device__ float g_scratch[SCRATCH_F];

// ---------------- helpers ----------------
__global__ void zero4_kernel(float4* __restrict__ p, int n4) {
    int i = blockIdx.x * blockDim.x + threadIdx.x;
    if (i < n4) p[i] = make_float4(0.f, 0.f, 0.f, 0.f);
}

// agg <- broadcast bias ; s1|s2 <- 0   (agg|s1|s2 contiguous)
__global__ void init_agg(float4* __restrict__ agg4, const float4* __restrict__ bias4) {
    int i = blockIdx.x * blockDim.x + threadIdx.x;
    const int NA = NN * HID / 4;
    if (i < NA) agg4[i] = bias4[i & 31];
    else if (i < NA + 2 * NN / 4) agg4[i] = make_float4(0.f, 0.f, 0.f, 0.f);
}

// fused warp-aggregated degree count for both edge lists (deg2 = deg + NN)
__global__ void count_deg_both(const int* __restrict__ row1, int E1,
                               const int* __restrict__ row2, int E2,
                               float* __restrict__ deg) {
    int e = blockIdx.x * blockDim.x + threadIdx.x;
    if (e >= E1 + E2) return;
    int key = (e < E1) ? row1[e] : (NN + row2[e - E1]);
    unsigned m = __match_any_sync(__activemask(), key);
    if ((threadIdx.x & 31) == (__ffs(m) - 1)) atomicAdd(&deg[key], (float)__popc(m));
}

__device__ __forceinline__ float warp_red(float s) {
#pragma unroll
    for (int off = 16; off; off >>= 1) s += __shfl_xor_sync(0xffffffffu, s, off);
    return s;
}

__device__ __forceinline__ float4 relu4(float4 v) {
    return make_float4(fmaxf(v.x, 0.f), fmaxf(v.y, 0.f), fmaxf(v.z, 0.f), fmaxf(v.w, 0.f));
}

// split f into hi (bf16) + lo (bf16 of residual); return packed ushorts
__device__ __forceinline__ void split_bf16(float f, unsigned short& h, unsigned short& l) {
    __nv_bfloat16 bh = __float2bfloat16_rn(f);
    float r = f - __bfloat162float(bh);
    __nv_bfloat16 bl = __float2bfloat16_rn(r);
    h = __bfloat16_as_ushort(bh);
    l = __bfloat16_as_ushort(bl);
}
__device__ __forceinline__ unsigned pack2(unsigned short lo_even, unsigned short hi_odd) {
    return ((unsigned)hi_odd << 16) | (unsigned)lo_even;   // lower 16 = even-k element
}

// ---------------- split-BF16 tensor GEMM (m16n8k16, 3-term) ----------------
// MODE 0: C = A @ W
// MODE 1: dual — blocks [0,GB): C=A@W ; [GB,2GB): C2=A2@W   (shared W)
// MODE 2: fused h-update: Aupd = (A + g1*relu(agg) + g2*skip)/(1+g1+g2),
//         writes Aupd back to hout and computes C = Aupd @ W
// smem holds k-pair-packed bf16x2: X[p][m], p = k/2 within the 16-k chunk (p=0..7).
#define KCH 16
#define SPAD 136
template<int MODE>
__global__ __launch_bounds__(256, 2) void gemm_k(
    const float* A, const float* __restrict__ A2,
    const float* __restrict__ W, float* __restrict__ C, float* __restrict__ C2,
    const float* __restrict__ agg, const float* __restrict__ skip,
    const float* __restrict__ s1, const float* __restrict__ s2,
    const float* __restrict__ deg1, const float* __restrict__ deg2,
    float* hout, int N) {
    __shared__ unsigned As_hi[8 * SPAD], As_lo[8 * SPAD];   // [k-pair][m]
    __shared__ unsigned Wv_hi[8 * SPAD], Wv_lo[8 * SPAD];   // [k-pair][n]
    __shared__ float cg1[128], cg2[128], cid[128];

    const int tid = threadIdx.x;
    const int lane = tid & 31;
    const int warp = tid >> 5;
    const int g = lane >> 2;       // 0..7
    const int t = lane & 3;        // 0..3
    const int mbase = warp * 16;

    const float* Ap = A;
    float* Cp = C;
    int rowBase;
    if (MODE == 1) {
        if (blockIdx.x < GB) rowBase = blockIdx.x * 128;
        else { Ap = A2; Cp = C2; rowBase = (blockIdx.x - GB) * 128; }
    } else {
        rowBase = blockIdx.x * 128;
    }

    if (MODE == 2) {
        if (tid < 128) {
            int r = rowBase + tid;
            float G1 = 0.f, G2 = 0.f, ID = 1.f;
            if (r < N) {
                G1 = tanhf(s1[r] / (deg1[r] + 1e-10f));
                G2 = tanhf(s2[r] / (deg2[r] + 1e-10f));
                ID = 1.0f / (1.0f + G1 + G2);
            }
            cg1[tid] = G1; cg2[tid] = G2; cid[tid] = ID;
        }
        __syncthreads();
    }

    float acc[16][4];
#pragma unroll
    for (int n = 0; n < 16; n++)
#pragma unroll
        for (int j = 0; j < 4; j++) acc[n][j] = 0.0f;

    float4 pa[2];
    float2 pwe[2], pwo[2];

    auto loadA = [&](int k0) {
#pragma unroll
        for (int tt = 0; tt < 2; tt++) {
            int idx = tid + tt * 256;
            int r = idx >> 2;
            int kq = (idx & 3) * 4;
            float4 v = make_float4(0.f, 0.f, 0.f, 0.f);
            if (rowBase + r < N) {
                size_t off = (size_t)(rowBase + r) * HID + k0 + kq;
                if (MODE == 2) {
                    float4 h4 = *reinterpret_cast<const float4*>(&Ap[off]);
                    float4 a4 = relu4(*reinterpret_cast<const float4*>(&agg[off]));
                    float4 k4 = *reinterpret_cast<const float4*>(&skip[off]);
                    float G1 = cg1[r], G2 = cg2[r], ID = cid[r];
                    v.x = (h4.x + G1 * a4.x + G2 * k4.x) * ID;
                    v.y = (h4.y + G1 * a4.y + G2 * k4.y) * ID;
                    v.z = (h4.z + G1 * a4.z + G2 * k4.z) * ID;
                    v.w = (h4.w + G1 * a4.w + G2 * k4.w) * ID;
                    *reinterpret_cast<float4*>(&hout[off]) = v;
                } else {
                    v = *reinterpret_cast<const float4*>(&Ap[off]);
                }
            }
            pa[tt] = v;
        }
    };
    // W rows come in adjacent pairs (even k row, odd k row) so bf16x2 packs along k
    auto loadW = [&](int k0) {
#pragma unroll
        for (int tt = 0; tt < 2; tt++) {
            int u = tid + tt * 256;          // 0..511
            int p = u >> 6;                  // k-pair 0..7
            int nc = (u & 63) * 2;           // col base
            pwe[tt] = *reinterpret_cast<const float2*>(&W[(size_t)(k0 + 2 * p) * HID + nc]);
            pwo[tt] = *reinterpret_cast<const float2*>(&W[(size_t)(k0 + 2 * p + 1) * HID + nc]);
        }
    };

    loadA(0); loadW(0);

    for (int k0 = 0; k0 < HID; k0 += KCH) {
        // ---- smem fill: split to bf16 hi/lo, pack k-pairs ----
#pragma unroll
        for (int tt = 0; tt < 2; tt++) {
            int idx = tid + tt * 256;
            int r = idx >> 2;
            int p0 = (idx & 3) * 2;          // k-pair index of f[0],f[1]
            float f[4] = {pa[tt].x, pa[tt].y, pa[tt].z, pa[tt].w};
            unsigned short h[4], l[4];
#pragma unroll
            for (int j = 0; j < 4; j++) split_bf16(f[j], h[j], l[j]);
            As_hi[p0 * SPAD + r] = pack2(h[0], h[1]);
            As_lo[p0 * SPAD + r] = pack2(l[0], l[1]);
            As_hi[(p0 + 1) * SPAD + r] = pack2(h[2], h[3]);
            As_lo[(p0 + 1) * SPAD + r] = pack2(l[2], l[3]);
        }
#pragma unroll
        for (int tt = 0; tt < 2; tt++) {
            int u = tid + tt * 256;
            int p = u >> 6;
            int nc = (u & 63) * 2;
            unsigned short he[2], le[2], ho[2], lo_[2];
            split_bf16(pwe[tt].x, he[0], le[0]);
            split_bf16(pwe[tt].y, he[1], le[1]);
            split_bf16(pwo[tt].x, ho[0], lo_[0]);
            split_bf16(pwo[tt].y, ho[1], lo_[1]);
            Wv_hi[p * SPAD + nc]     = pack2(he[0], ho[0]);
            Wv_lo[p * SPAD + nc]     = pack2(le[0], lo_[0]);
            Wv_hi[p * SPAD + nc + 1] = pack2(he[1], ho[1]);
            Wv_lo[p * SPAD + nc + 1] = pack2(le[1], lo_[1]);
        }
        __syncthreads();

        if (k0 + KCH < HID) { loadA(k0 + KCH); loadW(k0 + KCH); }

        // ---- one m16n8k16 per nt per term; k-pairs t (lo half) and t+4 (hi half) ----
        unsigned ah[4], al[4];
        ah[0] = As_hi[t * SPAD + mbase + g];
        ah[1] = As_hi[t * SPAD + mbase + g + 8];
        ah[2] = As_hi[(t + 4) * SPAD + mbase + g];
        ah[3] = As_hi[(t + 4) * SPAD + mbase + g + 8];
        al[0] = As_lo[t * SPAD + mbase + g];
        al[1] = As_lo[t * SPAD + mbase + g + 8];
        al[2] = As_lo[(t + 4) * SPAD + mbase + g];
        al[3] = As_lo[(t + 4) * SPAD + mbase + g + 8];
#pragma unroll
        for (int nt = 0; nt < 16; nt++) {
            int n = nt * 8 + g;
            unsigned bh0 = Wv_hi[t * SPAD + n];
            unsigned bh1 = Wv_hi[(t + 4) * SPAD + n];
            unsigned bl0 = Wv_lo[t * SPAD + n];
            unsigned bl1 = Wv_lo[(t + 4) * SPAD + n];
            asm volatile("mma.sync.aligned.m16n8k16.row.col.f32.bf16.bf16.f32 "
                         "{%0,%1,%2,%3}, {%4,%5,%6,%7}, {%8,%9}, {%0,%1,%2,%3};"
                         : "+f"(acc[nt][0]), "+f"(acc[nt][1]), "+f"(acc[nt][2]), "+f"(acc[nt][3])
                         : "r"(ah[0]), "r"(ah[1]), "r"(ah[2]), "r"(ah[3]), "r"(bh0), "r"(bh1));
            asm volatile("mma.sync.aligned.m16n8k16.row.col.f32.bf16.bf16.f32 "
                         "{%0,%1,%2,%3}, {%4,%5,%6,%7}, {%8,%9}, {%0,%1,%2,%3};"
                         : "+f"(acc[nt][0]), "+f"(acc[nt][1]), "+f"(acc[nt][2]), "+f"(acc[nt][3])
                         : "r"(ah[0]), "r"(ah[1]), "r"(ah[2]), "r"(ah[3]), "r"(bl0), "r"(bl1));
            asm volatile("mma.sync.aligned.m16n8k16.row.col.f32.bf16.bf16.f32 "
                         "{%0,%1,%2,%3}, {%4,%5,%6,%7}, {%8,%9}, {%0,%1,%2,%3};"
                         : "+f"(acc[nt][0]), "+f"(acc[nt][1]), "+f"(acc[nt][2]), "+f"(acc[nt][3])
                         : "r"(al[0]), "r"(al[1]), "r"(al[2]), "r"(al[3]), "r"(bh0), "r"(bh1));
        }
        __syncthreads();
    }

    int r0 = rowBase + mbase + g;
    int r1 = r0 + 8;
    if (r0 < N) {
#pragma unroll
        for (int nt = 0; nt < 16; nt++)
            *reinterpret_cast<float2*>(&Cp[(size_t)r0 * HID + nt * 8 + 2 * t]) =
                make_float2(acc[nt][0], acc[nt][1]);
    }
    if (r1 < N) {
#pragma unroll
        for (int nt = 0; nt < 16; nt++)
            *reinterpret_cast<float2*>(&Cp[(size_t)r1 * HID + nt * 8 + 2 * t]) =
                make_float2(acc[nt][2], acc[nt][3]);
    }
}

// ---------------- scatter: agg[col[e]] += m[row[e]] ----------------
__global__ void scatter_add(const float* __restrict__ m, const int* __restrict__ row,
                            const int* __restrict__ col, float* __restrict__ agg, int E) {
    int w = (blockIdx.x * blockDim.x + threadIdx.x) >> 5;
    if (w >= E) return;
    int lane = threadIdx.x & 31;
    int r = row[w];
    int c = col[w];
    float4 v = *reinterpret_cast<const float4*>(&m[(size_t)r * HID + lane * 4]);
    float* dst = &agg[(size_t)c * HID + lane * 4];
    asm volatile("red.global.add.v4.f32 [%0], {%1, %2, %3, %4};"
                 :: "l"(dst), "f"(v.x), "f"(v.y), "f"(v.z), "f"(v.w) : "memory");
}

// ---------------- fused gamma over both edge lists (relu applied on load) ----------------
#define G2_CHUNK 64
__global__ void gamma_both(const float* __restrict__ agg,
                           const int* __restrict__ row1, const int* __restrict__ col1,
                           float* __restrict__ s1, int E1, int blocks1,
                           const int* __restrict__ row2, const int* __restrict__ col2,
                           float* __restrict__ s2, int E2) {
    int lane = threadIdx.x & 31;
    if (blockIdx.x < blocks1) {
        int w = (blockIdx.x * blockDim.x + threadIdx.x) >> 5;
        if (w >= E1) return;
        int r = row1[w];
        int c = col1[w];
        float4 a = relu4(*reinterpret_cast<const float4*>(&agg[(size_t)r * HID + lane * 4]));
        float4 b = relu4(*reinterpret_cast<const float4*>(&agg[(size_t)c * HID + lane * 4]));
        float dx = a.x - b.x, dy = a.y - b.y, dz = a.z - b.z, dw = a.w - b.w;
        float s = warp_red(fmaf(dx, dx, fmaf(dy, dy, fmaf(dz, dz, dw * dw))));
        if (lane == 0) atomicAdd(&s1[r], s);
    } else {
        int w = (int)((((size_t)(blockIdx.x - blocks1) * blockDim.x) + threadIdx.x) >> 5);
        int base = w * G2_CHUNK;
        if (base >= E2) return;
        int end = min(base + G2_CHUNK, E2);
        int curR = row2[base];
        float4 ar = relu4(*reinterpret_cast<const float4*>(&agg[(size_t)curR * HID + lane * 4]));
        float acc = 0.0f;
        for (int e = base; e < end; e++) {
            int r = row2[e];
            if (r != curR) {
                float s = warp_red(acc);
                if (lane == 0) atomicAdd(&s2[curR], s);
                acc = 0.0f;
                curR = r;
                ar = relu4(*reinterpret_cast<const float4*>(&agg[(size_t)r * HID + lane * 4]));
            }
            int c = col2[e];
            float4 ac = relu4(*reinterpret_cast<const float4*>(&agg[(size_t)c * HID + lane * 4]));
            float dx = ar.x - ac.x, dy = ar.y - ac.y, dz = ar.z - ac.z, dw = ar.w - ac.w;
            acc += fmaf(dx, dx, fmaf(dy, dy, fmaf(dz, dz, dw * dw)));
        }
        float s = warp_red(acc);
        if (lane == 0) atomicAdd(&s2[curR], s);
    }
}

// ---------------- final GEMM with fused layer-2 h-update: out = h_upd @ fc_W + fc_b ----------------
#define ORPB 16
__global__ __launch_bounds__(640) void gemm_out_upd(
    const float* __restrict__ h, const float* __restrict__ agg, const float* __restrict__ skip,
    const float* __restrict__ s1, const float* __restrict__ s2,
    const float* __restrict__ deg1, const float* __restrict__ deg2,
    const float* __restrict__ W, const float* __restrict__ bias,
    float* __restrict__ C, int N) {
    __shared__ float Ws[HID * 41];
    __shared__ float bs[40];
    __shared__ float As[ORPB][HID];
    __shared__ float cg1[ORPB], cg2[ORPB], cid[ORPB];
    int tid = threadIdx.y * 40 + threadIdx.x;
    int rowBase = blockIdx.x * ORPB;

    for (int i = tid; i < HID * 40; i += 640) {
        int k = i / 40, n = i % 40;
        Ws[k * 41 + n] = W[i];
    }
    if (tid < 40) bs[tid] = bias[tid];
    if (tid < ORPB) {
        int r = rowBase + tid;
        float g1 = 0.f, g2 = 0.f, invd = 1.f;
        if (r < N) {
            g1 = tanhf(s1[r] / (deg1[r] + 1e-10f));
            g2 = tanhf(s2[r] / (deg2[r] + 1e-10f));
            invd = 1.0f / (1.0f + g1 + g2);
        }
        cg1[tid] = g1; cg2[tid] = g2; cid[tid] = invd;
    }
    __syncthreads();

    for (int i = tid; i < ORPB * HID; i += 640) {
        int rr = i >> 7, kk = i & (HID - 1);
        int r = rowBase + rr;
        float v = 0.0f;
        if (r < N) {
            size_t off = (size_t)r * HID + kk;
            v = (h[off] + cg1[rr] * fmaxf(agg[off], 0.f) + cg2[rr] * skip[off]) * cid[rr];
        }
        As[rr][kk] = v;
    }
    __syncthreads();

    int row = rowBase + threadIdx.y;
    if (row >= N) return;
    float acc = bs[threadIdx.x];
#pragma unroll
    for (int k = 0; k < HID; k++) acc = fmaf(As[threadIdx.y][k], Ws[k * 41 + threadIdx.x], acc);
    C[(size_t)row * 40 + threadIdx.x] = acc;
}

// ---------------- launcher ----------------
extern "C" void kernel_launch(void* const* d_in, const int* in_sizes, int n_in,
                              void* d_out, int out_size) {
    const float* x       = (const float*)d_in[0];
    const float* x0      = (const float*)d_in[1];
    const int*   ei      = (const int*)d_in[2];
    const int*   ei2     = (const int*)d_in[3];
    const float* in_W    = (const float*)d_in[4];
    const float* skip_W  = (const float*)d_in[5];
    const float* conv_W  = (const float*)d_in[6];
    const float* conv_b  = (const float*)d_in[7];
    const float* fc_W    = (const float*)d_in[8];
    const float* fc_b    = (const float*)d_in[9];
    float* out = (float*)d_out;

    const int E1 = in_sizes[2] / 2;
    const int E2 = in_sizes[3] / 2;
    const int* row1 = ei;
    const int* col1 = ei + E1;
    const int* row2 = ei2;
    const int* col2 = ei2 + E2;

    float* base;
    cudaGetSymbolAddress((void**)&base, g_scratch);
    float* h    = base + OFF_H;
    float* m    = base + OFF_M;
    float* skip = base + OFF_SKIP;
    float* agg  = base + OFF_AGG;
    float* s1   = base + OFF_S1;
    float* s2   = base + OFF_S2;
    float* deg1 = base + OFF_DEG1;
    float* deg2 = base + OFF_DEG2;

    const int NTH = 256;

    zero4_kernel<<<(2 * NN / 4 + NTH - 1) / NTH, NTH>>>((float4*)deg1, 2 * NN / 4);
    count_deg_both<<<(E1 + E2 + NTH - 1) / NTH, NTH>>>(row1, E1, row2, E2, deg1);

    // dual input projection: h = x@in_W, m(=h0) = x0@in_W (shared W)
    gemm_k<1><<<2 * GB, NTH>>>(x, x0, in_W, h, m,
                               nullptr, nullptr, nullptr, nullptr, nullptr, nullptr, nullptr, NN);
    // x_skip = h0 @ skip_W
    gemm_k<0><<<GB, NTH>>>(m, nullptr, skip_W, skip, nullptr,
                           nullptr, nullptr, nullptr, nullptr, nullptr, nullptr, nullptr, NN);

    const int initGrid = (NN * HID / 4 + 2 * NN / 4 + NTH - 1) / NTH;
    const int blocks1 = (int)(((size_t)E1 * 32 + NTH - 1) / NTH);
    const int warps2  = (E2 + G2_CHUNK - 1) / G2_CHUNK;
    const int blocks2 = (warps2 * 32 + NTH - 1) / NTH;

    // ---- layer 0 ----
    gemm_k<0><<<GB, NTH>>>(h, nullptr, conv_W, m, nullptr,
                           nullptr, nullptr, nullptr, nullptr, nullptr, nullptr, nullptr, NN);
    init_agg<<<initGrid, NTH>>>((float4*)agg, (const float4*)(conv_b));
    scatter_add<<<(int)(((size_t)E1 * 32 + NTH - 1) / NTH), NTH>>>(m, row1, col1, agg, E1);
    gamma_both<<<blocks1 + blocks2, NTH>>>(agg, row1, col1, s1, E1, blocks1, row2, col2, s2, E2);

    // ---- layer 1 (h-update fused into conv GEMM) ----
    gemm_k<2><<<GB, NTH>>>(h, nullptr, conv_W + (size_t)HID * HID, m, nullptr,
                           agg, skip, s1, s2, deg1, deg2, h, NN);
    init_agg<<<initGrid, NTH>>>((float4*)agg, (const float4*)(conv_b + HID));
    scatter_add<<<(int)(((size_t)E1 * 32 + NTH - 1) / NTH), NTH>>>(m, row1, col1, agg, E1);
    gamma_both<<<blocks1 + blocks2, NTH>>>(agg, row1, col1, s1, E1, blocks1, row2, col2, s2, E2);

    // ---- output (layer-2 h-update fused) ----
    gemm_out_upd<<<(NN + ORPB - 1) / ORPB, dim3(40, ORPB)>>>(
        h, agg, skip, s1, s2, deg1, deg2, fc_W, fc_b, out, NN);
}

// round 10
// speedup vs baseline: 1.2416x; 1.0092x over previous
#include <cuda_runtime.h>
#include <cuda_bf16.h>
#include <cuda_fp16.h>
#include <math.h>

#define NN 20000
#define HID 128
#define GBM 313         // GEMM blocks for 20000 rows @64/tile

// ---------------- single scratch buffer ----------------
#define OFF_H     0
#define OFF_M     2560000
#define OFF_SKIP  5120000
#define OFF_AGG   7680000
#define OFF_S1    10240000   // contiguous after agg: agg | s1 | s2
#define OFF_S2    10260000
#define OFF_DEG1  10280000   // contiguous: deg1 | deg2
#define OFF_DEG2  10300000
#define OFF_AGGH  10320000   // fp16 mirror of relu(agg): NN*HID halfs = 1.28M floats
#define SCRATCH_F 11600000
__device__ float g_scratch[SCRATCH_F];

// ---------------- helpers ----------------
__global__ void zero4_kernel(float4* __restrict__ p, int n4) {
    int i = blockIdx.x * blockDim.x + threadIdx.x;
    if (i < n4) p[i] = make_float4(0.f, 0.f, 0.f, 0.f);
}

// agg <- broadcast bias ; s1|s2 <- 0   (agg|s1|s2 contiguous)
__global__ void init_agg(float4* __restrict__ agg4, const float4* __restrict__ bias4) {
    int i = blockIdx.x * blockDim.x + threadIdx.x;
    const int NA = NN * HID / 4;
    if (i < NA) agg4[i] = bias4[i & 31];
    else if (i < NA + 2 * NN / 4) agg4[i] = make_float4(0.f, 0.f, 0.f, 0.f);
}

// fp16 mirror: aggh = (half)relu(agg)
__global__ void relu_fp16(const float4* __restrict__ agg4, uint2* __restrict__ aggh) {
    int i = blockIdx.x * blockDim.x + threadIdx.x;
    if (i >= NN * HID / 4) return;
    float4 v = agg4[i];
    __half2 a = __float22half2_rn(make_float2(fmaxf(v.x, 0.f), fmaxf(v.y, 0.f)));
    __half2 b = __float22half2_rn(make_float2(fmaxf(v.z, 0.f), fmaxf(v.w, 0.f)));
    uint2 o;
    o.x = *reinterpret_cast<unsigned*>(&a);
    o.y = *reinterpret_cast<unsigned*>(&b);
    aggh[i] = o;
}

// fused warp-aggregated degree count for both edge lists (deg2 = deg + NN)
__global__ void count_deg_both(const int* __restrict__ row1, int E1,
                               const int* __restrict__ row2, int E2,
                               float* __restrict__ deg) {
    int e = blockIdx.x * blockDim.x + threadIdx.x;
    if (e >= E1 + E2) return;
    int key = (e < E1) ? row1[e] : (NN + row2[e - E1]);
    unsigned m = __match_any_sync(__activemask(), key);
    if ((threadIdx.x & 31) == (__ffs(m) - 1)) atomicAdd(&deg[key], (float)__popc(m));
}

__device__ __forceinline__ float warp_red(float s) {
#pragma unroll
    for (int off = 16; off; off >>= 1) s += __shfl_xor_sync(0xffffffffu, s, off);
    return s;
}

__device__ __forceinline__ float4 relu4(float4 v) {
    return make_float4(fmaxf(v.x, 0.f), fmaxf(v.y, 0.f), fmaxf(v.z, 0.f), fmaxf(v.w, 0.f));
}

// load 4 halfs (uint2) -> float4
__device__ __forceinline__ float4 h4_to_f4(uint2 u) {
    __half2 a = *reinterpret_cast<__half2*>(&u.x);
    __half2 b = *reinterpret_cast<__half2*>(&u.y);
    float2 fa = __half22float2(a);
    float2 fb = __half22float2(b);
    return make_float4(fa.x, fa.y, fb.x, fb.y);
}

// split f into hi (bf16) + lo (bf16 of residual)
__device__ __forceinline__ void split_bf16(float f, unsigned short& h, unsigned short& l) {
    __nv_bfloat16 bh = __float2bfloat16_rn(f);
    float r = f - __bfloat162float(bh);
    __nv_bfloat16 bl = __float2bfloat16_rn(r);
    h = __bfloat16_as_ushort(bh);
    l = __bfloat16_as_ushort(bl);
}
__device__ __forceinline__ unsigned pack2(unsigned short lo_even, unsigned short hi_odd) {
    return ((unsigned)hi_odd << 16) | (unsigned)lo_even;
}

// ---------------- split-BF16 tensor GEMM, M=64 tile (m16n8k16, 3-term) ----------------
// 256 thr: warp wm = warp&3 covers rows wm*16..+15; wn = warp>>2 covers cols wn*64..+63.
// MODE 0: C = A @ W ; MODE 1: dual (shared W) ; MODE 2: fused h-update on A-load.
#define KCH 16
#define SPA 72     // A smem stride: [k-pair][m 0..63]
#define SPW 136    // W smem stride: [k-pair][n 0..127]
template<int MODE>
__global__ __launch_bounds__(256, 2) void gemm_k(
    const float* A, const float* __restrict__ A2,
    const float* __restrict__ W, float* __restrict__ C, float* __restrict__ C2,
    const float* __restrict__ agg, const float* __restrict__ skip,
    const float* __restrict__ s1, const float* __restrict__ s2,
    const float* __restrict__ deg1, const float* __restrict__ deg2,
    float* hout, int N) {
    __shared__ unsigned As_hi[8 * SPA], As_lo[8 * SPA];
    __shared__ unsigned Wv_hi[8 * SPW], Wv_lo[8 * SPW];
    __shared__ float cg1[64], cg2[64], cid[64];

    const int tid = threadIdx.x;
    const int lane = tid & 31;
    const int warp = tid >> 5;
    const int g = lane >> 2;
    const int t = lane & 3;
    const int wm = warp & 3;
    const int wn = warp >> 2;
    const int mbase = wm * 16;
    const int nbase = wn * 64;

    const float* Ap = A;
    float* Cp = C;
    int rowBase;
    if (MODE == 1) {
        if (blockIdx.x < GBM) rowBase = blockIdx.x * 64;
        else { Ap = A2; Cp = C2; rowBase = (blockIdx.x - GBM) * 64; }
    } else {
        rowBase = blockIdx.x * 64;
    }

    if (MODE == 2) {
        if (tid < 64) {
            int r = rowBase + tid;
            float G1 = 0.f, G2 = 0.f, ID = 1.f;
            if (r < N) {
                G1 = tanhf(s1[r] / (deg1[r] + 1e-10f));
                G2 = tanhf(s2[r] / (deg2[r] + 1e-10f));
                ID = 1.0f / (1.0f + G1 + G2);
            }
            cg1[tid] = G1; cg2[tid] = G2; cid[tid] = ID;
        }
        __syncthreads();
    }

    float acc[8][4];
#pragma unroll
    for (int n = 0; n < 8; n++)
#pragma unroll
        for (int j = 0; j < 4; j++) acc[n][j] = 0.0f;

    float4 pa;
    float2 pwe[2], pwo[2];

    auto loadA = [&](int k0) {
        int r = tid >> 2;
        int kq = (tid & 3) * 4;
        float4 v = make_float4(0.f, 0.f, 0.f, 0.f);
        if (rowBase + r < N) {
            size_t off = (size_t)(rowBase + r) * HID + k0 + kq;
            if (MODE == 2) {
                float4 h4 = *reinterpret_cast<const float4*>(&Ap[off]);
                float4 a4 = relu4(*reinterpret_cast<const float4*>(&agg[off]));
                float4 k4 = *reinterpret_cast<const float4*>(&skip[off]);
                float G1 = cg1[r], G2 = cg2[r], ID = cid[r];
                v.x = (h4.x + G1 * a4.x + G2 * k4.x) * ID;
                v.y = (h4.y + G1 * a4.y + G2 * k4.y) * ID;
                v.z = (h4.z + G1 * a4.z + G2 * k4.z) * ID;
                v.w = (h4.w + G1 * a4.w + G2 * k4.w) * ID;
                *reinterpret_cast<float4*>(&hout[off]) = v;
            } else {
                v = *reinterpret_cast<const float4*>(&Ap[off]);
            }
        }
        pa = v;
    };
    auto loadW = [&](int k0) {
#pragma unroll
        for (int tt = 0; tt < 2; tt++) {
            int u = tid + tt * 256;
            int p = u >> 6;
            int nc = (u & 63) * 2;
            pwe[tt] = *reinterpret_cast<const float2*>(&W[(size_t)(k0 + 2 * p) * HID + nc]);
            pwo[tt] = *reinterpret_cast<const float2*>(&W[(size_t)(k0 + 2 * p + 1) * HID + nc]);
        }
    };

    loadA(0); loadW(0);

    for (int k0 = 0; k0 < HID; k0 += KCH) {
        // ---- smem fill ----
        {
            int r = tid >> 2;
            int p0 = (tid & 3) * 2;
            float f[4] = {pa.x, pa.y, pa.z, pa.w};
            unsigned short h[4], l[4];
#pragma unroll
            for (int j = 0; j < 4; j++) split_bf16(f[j], h[j], l[j]);
            As_hi[p0 * SPA + r] = pack2(h[0], h[1]);
            As_lo[p0 * SPA + r] = pack2(l[0], l[1]);
            As_hi[(p0 + 1) * SPA + r] = pack2(h[2], h[3]);
            As_lo[(p0 + 1) * SPA + r] = pack2(l[2], l[3]);
        }
#pragma unroll
        for (int tt = 0; tt < 2; tt++) {
            int u = tid + tt * 256;
            int p = u >> 6;
            int nc = (u & 63) * 2;
            unsigned short he[2], le[2], ho[2], lo_[2];
            split_bf16(pwe[tt].x, he[0], le[0]);
            split_bf16(pwe[tt].y, he[1], le[1]);
            split_bf16(pwo[tt].x, ho[0], lo_[0]);
            split_bf16(pwo[tt].y, ho[1], lo_[1]);
            Wv_hi[p * SPW + nc]     = pack2(he[0], ho[0]);
            Wv_lo[p * SPW + nc]     = pack2(le[0], lo_[0]);
            Wv_hi[p * SPW + nc + 1] = pack2(he[1], ho[1]);
            Wv_lo[p * SPW + nc + 1] = pack2(le[1], lo_[1]);
        }
        __syncthreads();

        if (k0 + KCH < HID) { loadA(k0 + KCH); loadW(k0 + KCH); }

        unsigned ah[4], al[4];
        ah[0] = As_hi[t * SPA + mbase + g];
        ah[1] = As_hi[t * SPA + mbase + g + 8];
        ah[2] = As_hi[(t + 4) * SPA + mbase + g];
        ah[3] = As_hi[(t + 4) * SPA + mbase + g + 8];
        al[0] = As_lo[t * SPA + mbase + g];
        al[1] = As_lo[t * SPA + mbase + g + 8];
        al[2] = As_lo[(t + 4) * SPA + mbase + g];
        al[3] = As_lo[(t + 4) * SPA + mbase + g + 8];
#pragma unroll
        for (int j = 0; j < 8; j++) {
            int n = nbase + j * 8 + g;
            unsigned bh0 = Wv_hi[t * SPW + n];
            unsigned bh1 = Wv_hi[(t + 4) * SPW + n];
            unsigned bl0 = Wv_lo[t * SPW + n];
            unsigned bl1 = Wv_lo[(t + 4) * SPW + n];
            asm volatile("mma.sync.aligned.m16n8k16.row.col.f32.bf16.bf16.f32 "
                         "{%0,%1,%2,%3}, {%4,%5,%6,%7}, {%8,%9}, {%0,%1,%2,%3};"
                         : "+f"(acc[j][0]), "+f"(acc[j][1]), "+f"(acc[j][2]), "+f"(acc[j][3])
                         : "r"(ah[0]), "r"(ah[1]), "r"(ah[2]), "r"(ah[3]), "r"(bh0), "r"(bh1));
            asm volatile("mma.sync.aligned.m16n8k16.row.col.f32.bf16.bf16.f32 "
                         "{%0,%1,%2,%3}, {%4,%5,%6,%7}, {%8,%9}, {%0,%1,%2,%3};"
                         : "+f"(acc[j][0]), "+f"(acc[j][1]), "+f"(acc[j][2]), "+f"(acc[j][3])
                         : "r"(ah[0]), "r"(ah[1]), "r"(ah[2]), "r"(ah[3]), "r"(bl0), "r"(bl1));
            asm volatile("mma.sync.aligned.m16n8k16.row.col.f32.bf16.bf16.f32 "
                         "{%0,%1,%2,%3}, {%4,%5,%6,%7}, {%8,%9}, {%0,%1,%2,%3};"
                         : "+f"(acc[j][0]), "+f"(acc[j][1]), "+f"(acc[j][2]), "+f"(acc[j][3])
                         : "r"(al[0]), "r"(al[1]), "r"(al[2]), "r"(al[3]), "r"(bh0), "r"(bh1));
        }
        __syncthreads();
    }

    int r0 = rowBase + mbase + g;
    int r1 = r0 + 8;
    if (r0 < N) {
#pragma unroll
        for (int j = 0; j < 8; j++)
            *reinterpret_cast<float2*>(&Cp[(size_t)r0 * HID + nbase + j * 8 + 2 * t]) =
                make_float2(acc[j][0], acc[j][1]);
    }
    if (r1 < N) {
#pragma unroll
        for (int j = 0; j < 8; j++)
            *reinterpret_cast<float2*>(&Cp[(size_t)r1 * HID + nbase + j * 8 + 2 * t]) =
                make_float2(acc[j][2], acc[j][3]);
    }
}

// ---------------- scatter: agg[col[e]] += m[row[e]] ----------------
__global__ void scatter_add(const float* __restrict__ m, const int* __restrict__ row,
                            const int* __restrict__ col, float* __restrict__ agg, int E) {
    int w = (blockIdx.x * blockDim.x + threadIdx.x) >> 5;
    if (w >= E) return;
    int lane = threadIdx.x & 31;
    int r = row[w];
    int c = col[w];
    float4 v = *reinterpret_cast<const float4*>(&m[(size_t)r * HID + lane * 4]);
    float* dst = &agg[(size_t)c * HID + lane * 4];
    asm volatile("red.global.add.v4.f32 [%0], {%1, %2, %3, %4};"
                 :: "l"(dst), "f"(v.x), "f"(v.y), "f"(v.z), "f"(v.w) : "memory");
}

// ---------------- fused gamma over both edge lists, fp16 gathers ----------------
#define G2_CHUNK 64
__global__ void gamma_both(const uint2* __restrict__ aggh,   // NN x 32 uint2 (128 halfs/row)
                           const int* __restrict__ row1, const int* __restrict__ col1,
                           float* __restrict__ s1, int E1, int blocks1,
                           const int* __restrict__ row2, const int* __restrict__ col2,
                           float* __restrict__ s2, int E2) {
    int lane = threadIdx.x & 31;
    if (blockIdx.x < blocks1) {
        int w = (blockIdx.x * blockDim.x + threadIdx.x) >> 5;
        if (w >= E1) return;
        int r = row1[w];
        int c = col1[w];
        float4 a = h4_to_f4(aggh[(size_t)r * 32 + lane]);
        float4 b = h4_to_f4(aggh[(size_t)c * 32 + lane]);
        float dx = a.x - b.x, dy = a.y - b.y, dz = a.z - b.z, dw = a.w - b.w;
        float s = warp_red(fmaf(dx, dx, fmaf(dy, dy, fmaf(dz, dz, dw * dw))));
        if (lane == 0) atomicAdd(&s1[r], s);
    } else {
        int w = (int)((((size_t)(blockIdx.x - blocks1) * blockDim.x) + threadIdx.x) >> 5);
        int base = w * G2_CHUNK;
        if (base >= E2) return;
        int end = min(base + G2_CHUNK, E2);
        int curR = row2[base];
        float4 ar = h4_to_f4(aggh[(size_t)curR * 32 + lane]);
        float acc = 0.0f;
        for (int e = base; e < end; e++) {
            int r = row2[e];
            if (r != curR) {
                float s = warp_red(acc);
                if (lane == 0) atomicAdd(&s2[curR], s);
                acc = 0.0f;
                curR = r;
                ar = h4_to_f4(aggh[(size_t)r * 32 + lane]);
            }
            int c = col2[e];
            float4 ac = h4_to_f4(aggh[(size_t)c * 32 + lane]);
            float dx = ar.x - ac.x, dy = ar.y - ac.y, dz = ar.z - ac.z, dw = ar.w - ac.w;
            acc += fmaf(dx, dx, fmaf(dy, dy, fmaf(dz, dz, dw * dw)));
        }
        float s = warp_red(acc);
        if (lane == 0) atomicAdd(&s2[curR], s);
    }
}

// ---------------- final GEMM with fused layer-2 h-update: out = h_upd @ fc_W + fc_b ----------------
#define ORPB 16
__global__ __launch_bounds__(640) void gemm_out_upd(
    const float* __restrict__ h, const float* __restrict__ agg, const float* __restrict__ skip,
    const float* __restrict__ s1, const float* __restrict__ s2,
    const float* __restrict__ deg1, const float* __restrict__ deg2,
    const float* __restrict__ W, const float* __restrict__ bias,
    float* __restrict__ C, int N) {
    __shared__ float Ws[HID * 41];
    __shared__ float bs[40];
    __shared__ float As[ORPB][HID];
    __shared__ float cg1[ORPB], cg2[ORPB], cid[ORPB];
    int tid = threadIdx.y * 40 + threadIdx.x;
    int rowBase = blockIdx.x * ORPB;

    for (int i = tid; i < HID * 40; i += 640) {
        int k = i / 40, n = i % 40;
        Ws[k * 41 + n] = W[i];
    }
    if (tid < 40) bs[tid] = bias[tid];
    if (tid < ORPB) {
        int r = rowBase + tid;
        float g1 = 0.f, g2 = 0.f, invd = 1.f;
        if (r < N) {
            g1 = tanhf(s1[r] / (deg1[r] + 1e-10f));
            g2 = tanhf(s2[r] / (deg2[r] + 1e-10f));
            invd = 1.0f / (1.0f + g1 + g2);
        }
        cg1[tid] = g1; cg2[tid] = g2; cid[tid] = invd;
    }
    __syncthreads();

    for (int i = tid; i < ORPB * HID; i += 640) {
        int rr = i >> 7, kk = i & (HID - 1);
        int r = rowBase + rr;
        float v = 0.0f;
        if (r < N) {
            size_t off = (size_t)r * HID + kk;
            v = (h[off] + cg1[rr] * fmaxf(agg[off], 0.f) + cg2[rr] * skip[off]) * cid[rr];
        }
        As[rr][kk] = v;
    }
    __syncthreads();

    int row = rowBase + threadIdx.y;
    if (row >= N) return;
    float acc = bs[threadIdx.x];
#pragma unroll
    for (int k = 0; k < HID; k++) acc = fmaf(As[threadIdx.y][k], Ws[k * 41 + threadIdx.x], acc);
    C[(size_t)row * 40 + threadIdx.x] = acc;
}

// ---------------- launcher ----------------
extern "C" void kernel_launch(void* const* d_in, const int* in_sizes, int n_in,
                              void* d_out, int out_size) {
    const float* x       = (const float*)d_in[0];
    const float* x0      = (const float*)d_in[1];
    const int*   ei      = (const int*)d_in[2];
    const int*   ei2     = (const int*)d_in[3];
    const float* in_W    = (const float*)d_in[4];
    const float* skip_W  = (const float*)d_in[5];
    const float* conv_W  = (const float*)d_in[6];
    const float* conv_b  = (const float*)d_in[7];
    const float* fc_W    = (const float*)d_in[8];
    const float* fc_b    = (const float*)d_in[9];
    float* out = (float*)d_out;

    const int E1 = in_sizes[2] / 2;
    const int E2 = in_sizes[3] / 2;
    const int* row1 = ei;
    const int* col1 = ei + E1;
    const int* row2 = ei2;
    const int* col2 = ei2 + E2;

    float* base;
    cudaGetSymbolAddress((void**)&base, g_scratch);
    float* h    = base + OFF_H;
    float* m    = base + OFF_M;
    float* skip = base + OFF_SKIP;
    float* agg  = base + OFF_AGG;
    float* s1   = base + OFF_S1;
    float* s2   = base + OFF_S2;
    float* deg1 = base + OFF_DEG1;
    float* deg2 = base + OFF_DEG2;
    uint2* aggh = (uint2*)(base + OFF_AGGH);

    const int NTH = 256;

    zero4_kernel<<<(2 * NN / 4 + NTH - 1) / NTH, NTH>>>((float4*)deg1, 2 * NN / 4);
    count_deg_both<<<(E1 + E2 + NTH - 1) / NTH, NTH>>>(row1, E1, row2, E2, deg1);

    // dual input projection: h = x@in_W, m(=h0) = x0@in_W (shared W)
    gemm_k<1><<<2 * GBM, NTH>>>(x, x0, in_W, h, m,
                                nullptr, nullptr, nullptr, nullptr, nullptr, nullptr, nullptr, NN);
    // x_skip = h0 @ skip_W
    gemm_k<0><<<GBM, NTH>>>(m, nullptr, skip_W, skip, nullptr,
                            nullptr, nullptr, nullptr, nullptr, nullptr, nullptr, nullptr, NN);

    const int initGrid = (NN * HID / 4 + 2 * NN / 4 + NTH - 1) / NTH;
    const int cvtGrid  = (NN * HID / 4 + NTH - 1) / NTH;
    const int blocks1 = (int)(((size_t)E1 * 32 + NTH - 1) / NTH);
    const int warps2  = (E2 + G2_CHUNK - 1) / G2_CHUNK;
    const int blocks2 = (warps2 * 32 + NTH - 1) / NTH;

    // ---- layer 0 ----
    gemm_k<0><<<GBM, NTH>>>(h, nullptr, conv_W, m, nullptr,
                            nullptr, nullptr, nullptr, nullptr, nullptr, nullptr, nullptr, NN);
    init_agg<<<initGrid, NTH>>>((float4*)agg, (const float4*)(conv_b));
    scatter_add<<<(int)(((size_t)E1 * 32 + NTH - 1) / NTH), NTH>>>(m, row1, col1, agg, E1);
    relu_fp16<<<cvtGrid, NTH>>>((const float4*)agg, aggh);
    gamma_both<<<blocks1 + blocks2, NTH>>>(aggh, row1, col1, s1, E1, blocks1, row2, col2, s2, E2);

    // ---- layer 1 (h-update fused into conv GEMM) ----
    gemm_k<2><<<GBM, NTH>>>(h, nullptr, conv_W + (size_t)HID * HID, m, nullptr,
                            agg, skip, s1, s2, deg1, deg2, h, NN);
    init_agg<<<initGrid, NTH>>>((float4*)agg, (const float4*)(conv_b + HID));
    scatter_add<<<(int)(((size_t)E1 * 32 + NTH - 1) / NTH), NTH>>>(m, row1, col1, agg, E1);
    relu_fp16<<<cvtGrid, NTH>>>((const float4*)agg, aggh);
    gamma_both<<<blocks1 + blocks2, NTH>>>(aggh, row1, col1, s1, E1, blocks1, row2, col2, s2, E2);

    // ---- output (layer-2 h-update fused) ----
    gemm_out_upd<<<(NN + ORPB - 1) / ORPB, dim3(40, ORPB)>>>(
        h, agg, skip, s1, s2, deg1, deg2, fc_W, fc_b, out, NN);
}

// round 11
// speedup vs baseline: 1.2960x; 1.0438x over previous
#include <cuda_runtime.h>
#include <cuda_bf16.h>
#include <cuda_fp16.h>
#include <math.h>

#define NN 20000
#define HID 128
#define GBM 313         // GEMM blocks for 20000 rows @64/tile

// ---------------- single scratch buffer ----------------
#define OFF_H     0
#define OFF_M     2560000
#define OFF_SKIP  5120000
#define OFF_AGG   7680000
#define OFF_S1    10240000   // contiguous after agg: agg | s1 | s2
#define OFF_S2    10260000
#define OFF_DEG1  10280000   // contiguous: deg1 | deg2
#define OFF_DEG2  10300000
#define OFF_AGGH  10320000   // fp16 mirror of relu(agg)
#define OFF_WC1   11600000   // in_W @ skip_W   (128x128 fp32)
#define OFF_WC2   11616400   // in_W @ conv_W0  (128x128 fp32)
#define OFF_WPK   11632800   // packed bf16 hi/lo weights: 4 mats x 16384 words
#define SCRATCH_F 11698400
__device__ float g_scratch[SCRATCH_F];

// ---------------- helpers ----------------
__global__ void zero4_kernel(float4* __restrict__ p, int n4) {
    int i = blockIdx.x * blockDim.x + threadIdx.x;
    if (i < n4) p[i] = make_float4(0.f, 0.f, 0.f, 0.f);
}

// agg <- broadcast bias ; s1|s2 <- 0   (agg|s1|s2 contiguous)
__global__ void init_agg(float4* __restrict__ agg4, const float4* __restrict__ bias4) {
    int i = blockIdx.x * blockDim.x + threadIdx.x;
    const int NA = NN * HID / 4;
    if (i < NA) agg4[i] = bias4[i & 31];
    else if (i < NA + 2 * NN / 4) agg4[i] = make_float4(0.f, 0.f, 0.f, 0.f);
}

// fp16 mirror: aggh = (half)relu(agg)
__global__ void relu_fp16(const float4* __restrict__ agg4, uint2* __restrict__ aggh) {
    int i = blockIdx.x * blockDim.x + threadIdx.x;
    if (i >= NN * HID / 4) return;
    float4 v = agg4[i];
    __half2 a = __float22half2_rn(make_float2(fmaxf(v.x, 0.f), fmaxf(v.y, 0.f)));
    __half2 b = __float22half2_rn(make_float2(fmaxf(v.z, 0.f), fmaxf(v.w, 0.f)));
    uint2 o;
    o.x = *reinterpret_cast<unsigned*>(&a);
    o.y = *reinterpret_cast<unsigned*>(&b);
    aggh[i] = o;
}

// fused warp-aggregated degree count for both edge lists (deg2 = deg + NN)
__global__ void count_deg_both(const int* __restrict__ row1, int E1,
                               const int* __restrict__ row2, int E2,
                               float* __restrict__ deg) {
    int e = blockIdx.x * blockDim.x + threadIdx.x;
    if (e >= E1 + E2) return;
    int key = (e < E1) ? row1[e] : (NN + row2[e - E1]);
    unsigned m = __match_any_sync(__activemask(), key);
    if ((threadIdx.x & 31) == (__ffs(m) - 1)) atomicAdd(&deg[key], (float)__popc(m));
}

__device__ __forceinline__ float warp_red(float s) {
#pragma unroll
    for (int off = 16; off; off >>= 1) s += __shfl_xor_sync(0xffffffffu, s, off);
    return s;
}

__device__ __forceinline__ float4 relu4(float4 v) {
    return make_float4(fmaxf(v.x, 0.f), fmaxf(v.y, 0.f), fmaxf(v.z, 0.f), fmaxf(v.w, 0.f));
}

__device__ __forceinline__ float4 h4_to_f4(uint2 u) {
    __half2 a = *reinterpret_cast<__half2*>(&u.x);
    __half2 b = *reinterpret_cast<__half2*>(&u.y);
    float2 fa = __half22float2(a);
    float2 fb = __half22float2(b);
    return make_float4(fa.x, fa.y, fb.x, fb.y);
}

__device__ __forceinline__ void split_bf16(float f, unsigned short& h, unsigned short& l) {
    __nv_bfloat16 bh = __float2bfloat16_rn(f);
    float r = f - __bfloat162float(bh);
    __nv_bfloat16 bl = __float2bfloat16_rn(r);
    h = __bfloat16_as_ushort(bh);
    l = __bfloat16_as_ushort(bl);
}
__device__ __forceinline__ unsigned pack2(unsigned short lo_even, unsigned short hi_odd) {
    return ((unsigned)hi_odd << 16) | (unsigned)lo_even;
}

// ---------------- tiny fp32 GEMM: Wc = A(128x128) @ B(128x128), 8 col-blocks/mat ----------------
__global__ void tiny_gemm(const float* __restrict__ A,
                          const float* __restrict__ B1, const float* __restrict__ B2,
                          float* __restrict__ C1, float* __restrict__ C2) {
    int mat = blockIdx.x >> 3;
    int colBase = (blockIdx.x & 7) * 16;
    const float* B = mat ? B2 : B1;
    float* C = mat ? C2 : C1;
    __shared__ float As[16][129];   // [k][r]
    __shared__ float Bs[16][16];
    int tid = threadIdx.x;          // 256
    int r = tid & 127;
    int cg = tid >> 7;              // 0/1
    float acc[8];
#pragma unroll
    for (int j = 0; j < 8; j++) acc[j] = 0.0f;
    for (int k0 = 0; k0 < 128; k0 += 16) {
        for (int i = tid; i < 128 * 16; i += 256) {
            int rr = i >> 4, kk = i & 15;
            As[kk][rr] = A[rr * 128 + k0 + kk];
        }
        if (tid < 256) {
            int kk = tid >> 4, cc = tid & 15;
            if (tid < 256) Bs[kk][cc] = B[(k0 + kk) * 128 + colBase + cc];
        }
        __syncthreads();
#pragma unroll
        for (int kk = 0; kk < 16; kk++) {
            float a = As[kk][r];
#pragma unroll
            for (int j = 0; j < 8; j++)
                acc[j] = fmaf(a, Bs[kk][cg * 8 + j], acc[j]);
        }
        __syncthreads();
    }
#pragma unroll
    for (int j = 0; j < 8; j++)
        C[r * 128 + colBase + cg * 8 + j] = acc[j];
}

// ---------------- prepack weights to bf16 hi/lo in frag layout ----------------
// wpk[mat*16384 + c*1024 + p*128 + n]        = pack2(hi(W[c*16+2p][n]), hi(W[c*16+2p+1][n]))
// wpk[mat*16384 + 8192 + c*1024 + p*128 + n] = same with lo
__global__ void prepack_w(const float* __restrict__ inW, const float* __restrict__ wc1,
                          const float* __restrict__ wc2, const float* __restrict__ convW1,
                          unsigned* __restrict__ wpk) {
    int idx = blockIdx.x * blockDim.x + threadIdx.x;
    if (idx >= 4 * 8192) return;
    int mat = idx >> 13;
    int rem = idx & 8191;
    int c = rem >> 10;
    int p = (rem >> 7) & 7;
    int n = rem & 127;
    const float* W = (mat == 0) ? inW : (mat == 1) ? wc1 : (mat == 2) ? wc2 : convW1;
    int k0 = c * 16 + 2 * p;
    float we = W[k0 * 128 + n];
    float wo = W[(k0 + 1) * 128 + n];
    unsigned short he, le, ho, lo_;
    split_bf16(we, he, le);
    split_bf16(wo, ho, lo_);
    wpk[mat * 16384 + rem] = pack2(he, ho);
    wpk[mat * 16384 + 8192 + rem] = pack2(le, lo_);
}

// ---------------- split-BF16 tensor GEMM, M=64 tile, pre-packed W ----------------
// MODE 3: triple — [0,GBM): C=A@mat0 ; [GBM,2GBM): C2=A2@mat1 ; [2GBM,3GBM): C3=A@mat2
// MODE 2: fused h-update on A-load, W=mat3, C=output
#define KCH 16
#define SPA 72
#define SPW 136
template<int MODE>
__global__ __launch_bounds__(256, 2) void gemm_k(
    const float* A, const float* __restrict__ A2, const unsigned* __restrict__ wpk,
    float* __restrict__ C, float* __restrict__ C2, float* __restrict__ C3,
    const float* __restrict__ agg, const float* __restrict__ skipb,
    const float* __restrict__ s1, const float* __restrict__ s2,
    const float* __restrict__ deg1, const float* __restrict__ deg2,
    float* hout, int N) {
    __shared__ unsigned As_hi[8 * SPA], As_lo[8 * SPA];
    __shared__ unsigned Wv_hi[8 * SPW], Wv_lo[8 * SPW];
    __shared__ float cg1[64], cg2[64], cid[64];

    const int tid = threadIdx.x;
    const int lane = tid & 31;
    const int warp = tid >> 5;
    const int g = lane >> 2;
    const int t = lane & 3;
    const int wm = warp & 3;
    const int wn = warp >> 2;
    const int mbase = wm * 16;
    const int nbase = wn * 64;

    const float* Ap = A;
    float* Cp = C;
    int mat, rb = blockIdx.x;
    if (MODE == 3) {
        if (rb < GBM) { mat = 0; }
        else if (rb < 2 * GBM) { mat = 1; Ap = A2; Cp = C2; rb -= GBM; }
        else { mat = 2; Cp = C3; rb -= 2 * GBM; }
    } else {
        mat = 3;
    }
    const int rowBase = rb * 64;
    const unsigned* Wh = wpk + mat * 16384;
    const unsigned* Wl = Wh + 8192;

    if (MODE == 2) {
        if (tid < 64) {
            int r = rowBase + tid;
            float G1 = 0.f, G2 = 0.f, ID = 1.f;
            if (r < N) {
                G1 = tanhf(s1[r] / (deg1[r] + 1e-10f));
                G2 = tanhf(s2[r] / (deg2[r] + 1e-10f));
                ID = 1.0f / (1.0f + G1 + G2);
            }
            cg1[tid] = G1; cg2[tid] = G2; cid[tid] = ID;
        }
        __syncthreads();
    }

    float acc[8][4];
#pragma unroll
    for (int n = 0; n < 8; n++)
#pragma unroll
        for (int j = 0; j < 4; j++) acc[n][j] = 0.0f;

    float4 pa;
    uint4 pwh, pwl;
    const int wp = tid >> 5;              // W fill: p = warp
    const int wnc = (tid & 31) * 4;       // W fill: 4 cols

    auto loadA = [&](int k0) {
        int r = tid >> 2;
        int kq = (tid & 3) * 4;
        float4 v = make_float4(0.f, 0.f, 0.f, 0.f);
        if (rowBase + r < N) {
            size_t off = (size_t)(rowBase + r) * HID + k0 + kq;
            if (MODE == 2) {
                float4 h4 = *reinterpret_cast<const float4*>(&Ap[off]);
                float4 a4 = relu4(*reinterpret_cast<const float4*>(&agg[off]));
                float4 k4 = *reinterpret_cast<const float4*>(&skipb[off]);
                float G1 = cg1[r], G2 = cg2[r], ID = cid[r];
                v.x = (h4.x + G1 * a4.x + G2 * k4.x) * ID;
                v.y = (h4.y + G1 * a4.y + G2 * k4.y) * ID;
                v.z = (h4.z + G1 * a4.z + G2 * k4.z) * ID;
                v.w = (h4.w + G1 * a4.w + G2 * k4.w) * ID;
                *reinterpret_cast<float4*>(&hout[off]) = v;
            } else {
                v = *reinterpret_cast<const float4*>(&Ap[off]);
            }
        }
        pa = v;
    };
    auto loadW = [&](int c) {
        pwh = *reinterpret_cast<const uint4*>(&Wh[c * 1024 + wp * 128 + wnc]);
        pwl = *reinterpret_cast<const uint4*>(&Wl[c * 1024 + wp * 128 + wnc]);
    };

    loadA(0); loadW(0);

    for (int c = 0; c < 8; c++) {
        // ---- smem fill ----
        {
            int r = tid >> 2;
            int p0 = (tid & 3) * 2;
            float f[4] = {pa.x, pa.y, pa.z, pa.w};
            unsigned short h[4], l[4];
#pragma unroll
            for (int j = 0; j < 4; j++) split_bf16(f[j], h[j], l[j]);
            As_hi[p0 * SPA + r] = pack2(h[0], h[1]);
            As_lo[p0 * SPA + r] = pack2(l[0], l[1]);
            As_hi[(p0 + 1) * SPA + r] = pack2(h[2], h[3]);
            As_lo[(p0 + 1) * SPA + r] = pack2(l[2], l[3]);
        }
        *reinterpret_cast<uint4*>(&Wv_hi[wp * SPW + wnc]) = pwh;
        *reinterpret_cast<uint4*>(&Wv_lo[wp * SPW + wnc]) = pwl;
        __syncthreads();

        if (c + 1 < 8) { loadA((c + 1) * KCH); loadW(c + 1); }

        unsigned ah[4], al[4];
        ah[0] = As_hi[t * SPA + mbase + g];
        ah[1] = As_hi[t * SPA + mbase + g + 8];
        ah[2] = As_hi[(t + 4) * SPA + mbase + g];
        ah[3] = As_hi[(t + 4) * SPA + mbase + g + 8];
        al[0] = As_lo[t * SPA + mbase + g];
        al[1] = As_lo[t * SPA + mbase + g + 8];
        al[2] = As_lo[(t + 4) * SPA + mbase + g];
        al[3] = As_lo[(t + 4) * SPA + mbase + g + 8];
#pragma unroll
        for (int j = 0; j < 8; j++) {
            int n = nbase + j * 8 + g;
            unsigned bh0 = Wv_hi[t * SPW + n];
            unsigned bh1 = Wv_hi[(t + 4) * SPW + n];
            unsigned bl0 = Wv_lo[t * SPW + n];
            unsigned bl1 = Wv_lo[(t + 4) * SPW + n];
            asm volatile("mma.sync.aligned.m16n8k16.row.col.f32.bf16.bf16.f32 "
                         "{%0,%1,%2,%3}, {%4,%5,%6,%7}, {%8,%9}, {%0,%1,%2,%3};"
                         : "+f"(acc[j][0]), "+f"(acc[j][1]), "+f"(acc[j][2]), "+f"(acc[j][3])
                         : "r"(ah[0]), "r"(ah[1]), "r"(ah[2]), "r"(ah[3]), "r"(bh0), "r"(bh1));
            asm volatile("mma.sync.aligned.m16n8k16.row.col.f32.bf16.bf16.f32 "
                         "{%0,%1,%2,%3}, {%4,%5,%6,%7}, {%8,%9}, {%0,%1,%2,%3};"
                         : "+f"(acc[j][0]), "+f"(acc[j][1]), "+f"(acc[j][2]), "+f"(acc[j][3])
                         : "r"(ah[0]), "r"(ah[1]), "r"(ah[2]), "r"(ah[3]), "r"(bl0), "r"(bl1));
            asm volatile("mma.sync.aligned.m16n8k16.row.col.f32.bf16.bf16.f32 "
                         "{%0,%1,%2,%3}, {%4,%5,%6,%7}, {%8,%9}, {%0,%1,%2,%3};"
                         : "+f"(acc[j][0]), "+f"(acc[j][1]), "+f"(acc[j][2]), "+f"(acc[j][3])
                         : "r"(al[0]), "r"(al[1]), "r"(al[2]), "r"(al[3]), "r"(bh0), "r"(bh1));
        }
        __syncthreads();
    }

    int r0 = rowBase + mbase + g;
    int r1 = r0 + 8;
    if (r0 < N) {
#pragma unroll
        for (int j = 0; j < 8; j++)
            *reinterpret_cast<float2*>(&Cp[(size_t)r0 * HID + nbase + j * 8 + 2 * t]) =
                make_float2(acc[j][0], acc[j][1]);
    }
    if (r1 < N) {
#pragma unroll
        for (int j = 0; j < 8; j++)
            *reinterpret_cast<float2*>(&Cp[(size_t)r1 * HID + nbase + j * 8 + 2 * t]) =
                make_float2(acc[j][2], acc[j][3]);
    }
}

// ---------------- scatter: agg[col[e]] += m[row[e]] ----------------
__global__ void scatter_add(const float* __restrict__ m, const int* __restrict__ row,
                            const int* __restrict__ col, float* __restrict__ agg, int E) {
    int w = (blockIdx.x * blockDim.x + threadIdx.x) >> 5;
    if (w >= E) return;
    int lane = threadIdx.x & 31;
    int r = row[w];
    int c = col[w];
    float4 v = *reinterpret_cast<const float4*>(&m[(size_t)r * HID + lane * 4]);
    float* dst = &agg[(size_t)c * HID + lane * 4];
    asm volatile("red.global.add.v4.f32 [%0], {%1, %2, %3, %4};"
                 :: "l"(dst), "f"(v.x), "f"(v.y), "f"(v.z), "f"(v.w) : "memory");
}

// ---------------- fused gamma over both edge lists, fp16 gathers ----------------
#define G2_CHUNK 64
__global__ void gamma_both(const uint2* __restrict__ aggh,
                           const int* __restrict__ row1, const int* __restrict__ col1,
                           float* __restrict__ s1, int E1, int blocks1,
                           const int* __restrict__ row2, const int* __restrict__ col2,
                           float* __restrict__ s2, int E2) {
    int lane = threadIdx.x & 31;
    if (blockIdx.x < blocks1) {
        int w = (blockIdx.x * blockDim.x + threadIdx.x) >> 5;
        if (w >= E1) return;
        int r = row1[w];
        int c = col1[w];
        float4 a = h4_to_f4(aggh[(size_t)r * 32 + lane]);
        float4 b = h4_to_f4(aggh[(size_t)c * 32 + lane]);
        float dx = a.x - b.x, dy = a.y - b.y, dz = a.z - b.z, dw = a.w - b.w;
        float s = warp_red(fmaf(dx, dx, fmaf(dy, dy, fmaf(dz, dz, dw * dw))));
        if (lane == 0) atomicAdd(&s1[r], s);
    } else {
        int w = (int)((((size_t)(blockIdx.x - blocks1) * blockDim.x) + threadIdx.x) >> 5);
        int base = w * G2_CHUNK;
        if (base >= E2) return;
        int end = min(base + G2_CHUNK, E2);
        int curR = row2[base];
        float4 ar = h4_to_f4(aggh[(size_t)curR * 32 + lane]);
        float acc = 0.0f;
        for (int e = base; e < end; e++) {
            int r = row2[e];
            if (r != curR) {
                float s = warp_red(acc);
                if (lane == 0) atomicAdd(&s2[curR], s);
                acc = 0.0f;
                curR = r;
                ar = h4_to_f4(aggh[(size_t)r * 32 + lane]);
            }
            int c = col2[e];
            float4 ac = h4_to_f4(aggh[(size_t)c * 32 + lane]);
            float dx = ar.x - ac.x, dy = ar.y - ac.y, dz = ar.z - ac.z, dw = ar.w - ac.w;
            acc += fmaf(dx, dx, fmaf(dy, dy, fmaf(dz, dz, dw * dw)));
        }
        float s = warp_red(acc);
        if (lane == 0) atomicAdd(&s2[curR], s);
    }
}

// ---------------- final GEMM with fused layer-2 h-update ----------------
#define ORPB 16
__global__ __launch_bounds__(640) void gemm_out_upd(
    const float* __restrict__ h, const float* __restrict__ agg, const float* __restrict__ skip,
    const float* __restrict__ s1, const float* __restrict__ s2,
    const float* __restrict__ deg1, const float* __restrict__ deg2,
    const float* __restrict__ W, const float* __restrict__ bias,
    float* __restrict__ C, int N) {
    __shared__ float Ws[HID * 41];
    __shared__ float bs[40];
    __shared__ float As[ORPB][HID];
    __shared__ float cg1[ORPB], cg2[ORPB], cid[ORPB];
    int tid = threadIdx.y * 40 + threadIdx.x;
    int rowBase = blockIdx.x * ORPB;

    for (int i = tid; i < HID * 40; i += 640) {
        int k = i / 40, n = i % 40;
        Ws[k * 41 + n] = W[i];
    }
    if (tid < 40) bs[tid] = bias[tid];
    if (tid < ORPB) {
        int r = rowBase + tid;
        float g1 = 0.f, g2 = 0.f, invd = 1.f;
        if (r < N) {
            g1 = tanhf(s1[r] / (deg1[r] + 1e-10f));
            g2 = tanhf(s2[r] / (deg2[r] + 1e-10f));
            invd = 1.0f / (1.0f + g1 + g2);
        }
        cg1[tid] = g1; cg2[tid] = g2; cid[tid] = invd;
    }
    __syncthreads();

    for (int i = tid; i < ORPB * HID; i += 640) {
        int rr = i >> 7, kk = i & (HID - 1);
        int r = rowBase + rr;
        float v = 0.0f;
        if (r < N) {
            size_t off = (size_t)r * HID + kk;
            v = (h[off] + cg1[rr] * fmaxf(agg[off], 0.f) + cg2[rr] * skip[off]) * cid[rr];
        }
        As[rr][kk] = v;
    }
    __syncthreads();

    int row = rowBase + threadIdx.y;
    if (row >= N) return;
    float acc = bs[threadIdx.x];
#pragma unroll
    for (int k = 0; k < HID; k++) acc = fmaf(As[threadIdx.y][k], Ws[k * 41 + threadIdx.x], acc);
    C[(size_t)row * 40 + threadIdx.x] = acc;
}

// ---------------- launcher ----------------
extern "C" void kernel_launch(void* const* d_in, const int* in_sizes, int n_in,
                              void* d_out, int out_size) {
    const float* x       = (const float*)d_in[0];
    const float* x0      = (const float*)d_in[1];
    const int*   ei      = (const int*)d_in[2];
    const int*   ei2     = (const int*)d_in[3];
    const float* in_W    = (const float*)d_in[4];
    const float* skip_W  = (const float*)d_in[5];
    const float* conv_W  = (const float*)d_in[6];
    const float* conv_b  = (const float*)d_in[7];
    const float* fc_W    = (const float*)d_in[8];
    const float* fc_b    = (const float*)d_in[9];
    float* out = (float*)d_out;

    const int E1 = in_sizes[2] / 2;
    const int E2 = in_sizes[3] / 2;
    const int* row1 = ei;
    const int* col1 = ei + E1;
    const int* row2 = ei2;
    const int* col2 = ei2 + E2;

    float* base;
    cudaGetSymbolAddress((void**)&base, g_scratch);
    float* h    = base + OFF_H;
    float* m    = base + OFF_M;
    float* skip = base + OFF_SKIP;
    float* agg  = base + OFF_AGG;
    float* s1   = base + OFF_S1;
    float* s2   = base + OFF_S2;
    float* deg1 = base + OFF_DEG1;
    float* deg2 = base + OFF_DEG2;
    uint2* aggh = (uint2*)(base + OFF_AGGH);
    float* wc1  = base + OFF_WC1;
    float* wc2  = base + OFF_WC2;
    unsigned* wpk = (unsigned*)(base + OFF_WPK);

    const int NTH = 256;

    zero4_kernel<<<(2 * NN / 4 + NTH - 1) / NTH, NTH>>>((float4*)deg1, 2 * NN / 4);
    count_deg_both<<<(E1 + E2 + NTH - 1) / NTH, NTH>>>(row1, E1, row2, E2, deg1);

    // Wc1 = in_W @ skip_W ; Wc2 = in_W @ conv_W0  (fp32)
    tiny_gemm<<<16, NTH>>>(in_W, skip_W, conv_W, wc1, wc2);
    // pack mats: 0=in_W, 1=Wc1, 2=Wc2, 3=conv_W1
    prepack_w<<<(4 * 8192 + NTH - 1) / NTH, NTH>>>(in_W, wc1, wc2,
                                                   conv_W + (size_t)HID * HID, wpk);

    // triple: h = x@in_W ; skip = x0@Wc1 ; m = x@Wc2
    gemm_k<3><<<3 * GBM, NTH>>>(x, x0, wpk, h, skip, m,
                                nullptr, nullptr, nullptr, nullptr, nullptr, nullptr,
                                nullptr, NN);

    const int initGrid = (NN * HID / 4 + 2 * NN / 4 + NTH - 1) / NTH;
    const int cvtGrid  = (NN * HID / 4 + NTH - 1) / NTH;
    const int blocks1 = (int)(((size_t)E1 * 32 + NTH - 1) / NTH);
    const int warps2  = (E2 + G2_CHUNK - 1) / G2_CHUNK;
    const int blocks2 = (warps2 * 32 + NTH - 1) / NTH;

    // ---- layer 0 (m already computed) ----
    init_agg<<<initGrid, NTH>>>((float4*)agg, (const float4*)(conv_b));
    scatter_add<<<(int)(((size_t)E1 * 32 + NTH - 1) / NTH), NTH>>>(m, row1, col1, agg, E1);
    relu_fp16<<<cvtGrid, NTH>>>((const float4*)agg, aggh);
    gamma_both<<<blocks1 + blocks2, NTH>>>(aggh, row1, col1, s1, E1, blocks1, row2, col2, s2, E2);

    // ---- layer 1 (h-update fused into conv GEMM, W = mat3) ----
    gemm_k<2><<<GBM, NTH>>>(h, nullptr, wpk, m, nullptr, nullptr,
                            agg, skip, s1, s2, deg1, deg2, h, NN);
    init_agg<<<initGrid, NTH>>>((float4*)agg, (const float4*)(conv_b + HID));
    scatter_add<<<(int)(((size_t)E1 * 32 + NTH - 1) / NTH), NTH>>>(m, row1, col1, agg, E1);
    relu_fp16<<<cvtGrid, NTH>>>((const float4*)agg, aggh);
    gamma_both<<<blocks1 + blocks2, NTH>>>(aggh, row1, col1, s1, E1, blocks1, row2, col2, s2, E2);

    // ---- output (layer-2 h-update fused) ----
    gemm_out_upd<<<(NN + ORPB - 1) / ORPB, dim3(40, ORPB)>>>(
        h, agg, skip, s1, s2, deg1, deg2, fc_W, fc_b, out, NN);
}

// round 12
// speedup vs baseline: 1.3047x; 1.0067x over previous
#include <cuda_runtime.h>
#include <cuda_bf16.h>
#include <cuda_fp16.h>
#include <math.h>

#define NN 20000
#define HID 128
#define GBM 313         // GEMM blocks for 20000 rows @64/tile
#define NA4   (NN * HID / 4)          // float4s in agg
#define TOT4  (NA4 + 2 * NN / 4)      // agg | s1 | s2
#define INITB ((TOT4 + 255) / 256)    // init tail blocks

// ---------------- single scratch buffer ----------------
#define OFF_H     0
#define OFF_M     2560000
#define OFF_SKIP  5120000
#define OFF_AGG0  7680000    // agg0 | s1a | s2a   (2,600,000)
#define OFF_AGG1  10280000   // agg1 | s1b | s2b   (2,600,000)
#define OFF_DEG   12880000   // deg1 | deg2        (40,000)
#define OFF_AGGH  12920000   // fp16 mirror        (1,280,000)
#define OFF_WC1   14200000
#define OFF_WC2   14216384
#define OFF_WPK   14232768   // packed bf16 hi/lo weights: 4 mats x 16384 words
#define SCRATCH_F 14298304
__device__ float g_scratch[SCRATCH_F];

// ---------------- helpers ----------------
__device__ __forceinline__ float warp_red(float s) {
#pragma unroll
    for (int off = 16; off; off >>= 1) s += __shfl_xor_sync(0xffffffffu, s, off);
    return s;
}

__device__ __forceinline__ float4 relu4(float4 v) {
    return make_float4(fmaxf(v.x, 0.f), fmaxf(v.y, 0.f), fmaxf(v.z, 0.f), fmaxf(v.w, 0.f));
}

__device__ __forceinline__ float4 h4_to_f4(uint2 u) {
    __half2 a = *reinterpret_cast<__half2*>(&u.x);
    __half2 b = *reinterpret_cast<__half2*>(&u.y);
    float2 fa = __half22float2(a);
    float2 fb = __half22float2(b);
    return make_float4(fa.x, fa.y, fb.x, fb.y);
}

__device__ __forceinline__ void split_bf16(float f, unsigned short& h, unsigned short& l) {
    __nv_bfloat16 bh = __float2bfloat16_rn(f);
    float r = f - __bfloat162float(bh);
    __nv_bfloat16 bl = __float2bfloat16_rn(r);
    h = __bfloat16_as_ushort(bh);
    l = __bfloat16_as_ushort(bl);
}
__device__ __forceinline__ unsigned pack2(unsigned short lo_even, unsigned short hi_odd) {
    return ((unsigned)hi_odd << 16) | (unsigned)lo_even;
}

// ---------------- pre1: tiny fp32 GEMMs (blocks 0..15) + zero deg (blocks 16..) ----------------
// Wc1 = in_W @ skip_W ; Wc2 = in_W @ conv_W0
__global__ void pre1(const float* __restrict__ A,
                     const float* __restrict__ B1, const float* __restrict__ B2,
                     float* __restrict__ C1, float* __restrict__ C2,
                     float4* __restrict__ deg4) {
    int tid = threadIdx.x;
    if (blockIdx.x >= 16) {
        int i = (blockIdx.x - 16) * 256 + tid;
        if (i < 2 * NN / 4) deg4[i] = make_float4(0.f, 0.f, 0.f, 0.f);
        return;
    }
    int mat = blockIdx.x >> 3;
    int colBase = (blockIdx.x & 7) * 16;
    const float* B = mat ? B2 : B1;
    float* C = mat ? C2 : C1;
    __shared__ float As[16][129];
    __shared__ float Bs[16][16];
    int r = tid & 127;
    int cg = tid >> 7;
    float acc[8];
#pragma unroll
    for (int j = 0; j < 8; j++) acc[j] = 0.0f;
    for (int k0 = 0; k0 < 128; k0 += 16) {
        for (int i = tid; i < 128 * 16; i += 256) {
            int rr = i >> 4, kk = i & 15;
            As[kk][rr] = A[rr * 128 + k0 + kk];
        }
        {
            int kk = tid >> 4, cc = tid & 15;
            Bs[kk][cc] = B[(k0 + kk) * 128 + colBase + cc];
        }
        __syncthreads();
#pragma unroll
        for (int kk = 0; kk < 16; kk++) {
            float a = As[kk][r];
#pragma unroll
            for (int j = 0; j < 8; j++)
                acc[j] = fmaf(a, Bs[kk][cg * 8 + j], acc[j]);
        }
        __syncthreads();
    }
#pragma unroll
    for (int j = 0; j < 8; j++)
        C[r * 128 + colBase + cg * 8 + j] = acc[j];
}

// ---------------- pre2: prepack weights (blocks 0..127) + degree count (blocks 128..) ----------------
__global__ void pre2(const float* __restrict__ inW, const float* __restrict__ wc1,
                     const float* __restrict__ wc2, const float* __restrict__ convW1,
                     unsigned* __restrict__ wpk,
                     const int* __restrict__ row1, int E1,
                     const int* __restrict__ row2, int E2,
                     float* __restrict__ deg) {
    int tid = threadIdx.x;
    if (blockIdx.x >= 128) {
        int e = (blockIdx.x - 128) * 256 + tid;
        if (e >= E1 + E2) return;
        int key = (e < E1) ? row1[e] : (NN + row2[e - E1]);
        unsigned m = __match_any_sync(__activemask(), key);
        if ((tid & 31) == (__ffs(m) - 1)) atomicAdd(&deg[key], (float)__popc(m));
        return;
    }
    int idx = blockIdx.x * 256 + tid;   // < 32768
    int mat = idx >> 13;
    int rem = idx & 8191;
    int c = rem >> 10;
    int p = (rem >> 7) & 7;
    int n = rem & 127;
    const float* W = (mat == 0) ? inW : (mat == 1) ? wc1 : (mat == 2) ? wc2 : convW1;
    int k0 = c * 16 + 2 * p;
    float we = W[k0 * 128 + n];
    float wo = W[(k0 + 1) * 128 + n];
    unsigned short he, le, ho, lo_;
    split_bf16(we, he, le);
    split_bf16(wo, ho, lo_);
    wpk[mat * 16384 + rem] = pack2(he, ho);
    wpk[mat * 16384 + 8192 + rem] = pack2(le, lo_);
}

// ---------------- split-BF16 tensor GEMM, M=64 tile, pre-packed W, fused init tail ----------------
// MODE 3: triple — [0,GBM): C=A@mat0 ; [GBM,2GBM): C2=A2@mat1 ; [2GBM,3GBM): C3=A@mat2
// MODE 2: fused h-update on A-load, W=mat3, C=output
// Blocks >= gemmBlocks: init tail — initDst[agg]=bias bcast, [s1|s2]=0.
#define KCH 16
#define SPA 72
#define SPW 136
template<int MODE>
__global__ __launch_bounds__(256, 2) void gemm_k(
    const float* A, const float* __restrict__ A2, const unsigned* __restrict__ wpk,
    float* __restrict__ C, float* __restrict__ C2, float* __restrict__ C3,
    const float* __restrict__ agg, const float* __restrict__ skipb,
    const float* __restrict__ s1, const float* __restrict__ s2,
    const float* __restrict__ deg1, const float* __restrict__ deg2,
    float* hout,
    float4* __restrict__ initDst, const float4* __restrict__ bias4, int gemmBlocks,
    int N) {
    const int tid = threadIdx.x;

    if ((int)blockIdx.x >= gemmBlocks) {
        int i = ((int)blockIdx.x - gemmBlocks) * 256 + tid;
        if (i < NA4) initDst[i] = bias4[i & 31];
        else if (i < TOT4) initDst[i] = make_float4(0.f, 0.f, 0.f, 0.f);
        return;
    }

    __shared__ unsigned As_hi[8 * SPA], As_lo[8 * SPA];
    __shared__ unsigned Wv_hi[8 * SPW], Wv_lo[8 * SPW];
    __shared__ float cg1[64], cg2[64], cid[64];

    const int lane = tid & 31;
    const int warp = tid >> 5;
    const int g = lane >> 2;
    const int t = lane & 3;
    const int wm = warp & 3;
    const int wn = warp >> 2;
    const int mbase = wm * 16;
    const int nbase = wn * 64;

    const float* Ap = A;
    float* Cp = C;
    int mat, rb = blockIdx.x;
    if (MODE == 3) {
        if (rb < GBM) { mat = 0; }
        else if (rb < 2 * GBM) { mat = 1; Ap = A2; Cp = C2; rb -= GBM; }
        else { mat = 2; Cp = C3; rb -= 2 * GBM; }
    } else {
        mat = 3;
    }
    const int rowBase = rb * 64;
    const unsigned* Wh = wpk + mat * 16384;
    const unsigned* Wl = Wh + 8192;

    if (MODE == 2) {
        if (tid < 64) {
            int r = rowBase + tid;
            float G1 = 0.f, G2 = 0.f, ID = 1.f;
            if (r < N) {
                G1 = tanhf(s1[r] / (deg1[r] + 1e-10f));
                G2 = tanhf(s2[r] / (deg2[r] + 1e-10f));
                ID = 1.0f / (1.0f + G1 + G2);
            }
            cg1[tid] = G1; cg2[tid] = G2; cid[tid] = ID;
        }
        __syncthreads();
    }

    float acc[8][4];
#pragma unroll
    for (int n = 0; n < 8; n++)
#pragma unroll
        for (int j = 0; j < 4; j++) acc[n][j] = 0.0f;

    float4 pa;
    uint4 pwh, pwl;
    const int wp = tid >> 5;
    const int wnc = (tid & 31) * 4;

    auto loadA = [&](int k0) {
        int r = tid >> 2;
        int kq = (tid & 3) * 4;
        float4 v = make_float4(0.f, 0.f, 0.f, 0.f);
        if (rowBase + r < N) {
            size_t off = (size_t)(rowBase + r) * HID + k0 + kq;
            if (MODE == 2) {
                float4 h4 = *reinterpret_cast<const float4*>(&Ap[off]);
                float4 a4 = relu4(*reinterpret_cast<const float4*>(&agg[off]));
                float4 k4 = *reinterpret_cast<const float4*>(&skipb[off]);
                float G1 = cg1[r], G2 = cg2[r], ID = cid[r];
                v.x = (h4.x + G1 * a4.x + G2 * k4.x) * ID;
                v.y = (h4.y + G1 * a4.y + G2 * k4.y) * ID;
                v.z = (h4.z + G1 * a4.z + G2 * k4.z) * ID;
                v.w = (h4.w + G1 * a4.w + G2 * k4.w) * ID;
                *reinterpret_cast<float4*>(&hout[off]) = v;
            } else {
                v = *reinterpret_cast<const float4*>(&Ap[off]);
            }
        }
        pa = v;
    };
    auto loadW = [&](int c) {
        pwh = *reinterpret_cast<const uint4*>(&Wh[c * 1024 + wp * 128 + wnc]);
        pwl = *reinterpret_cast<const uint4*>(&Wl[c * 1024 + wp * 128 + wnc]);
    };

    loadA(0); loadW(0);

    for (int c = 0; c < 8; c++) {
        {
            int r = tid >> 2;
            int p0 = (tid & 3) * 2;
            float f[4] = {pa.x, pa.y, pa.z, pa.w};
            unsigned short h[4], l[4];
#pragma unroll
            for (int j = 0; j < 4; j++) split_bf16(f[j], h[j], l[j]);
            As_hi[p0 * SPA + r] = pack2(h[0], h[1]);
            As_lo[p0 * SPA + r] = pack2(l[0], l[1]);
            As_hi[(p0 + 1) * SPA + r] = pack2(h[2], h[3]);
            As_lo[(p0 + 1) * SPA + r] = pack2(l[2], l[3]);
        }
        *reinterpret_cast<uint4*>(&Wv_hi[wp * SPW + wnc]) = pwh;
        *reinterpret_cast<uint4*>(&Wv_lo[wp * SPW + wnc]) = pwl;
        __syncthreads();

        if (c + 1 < 8) { loadA((c + 1) * KCH); loadW(c + 1); }

        unsigned ah[4], al[4];
        ah[0] = As_hi[t * SPA + mbase + g];
        ah[1] = As_hi[t * SPA + mbase + g + 8];
        ah[2] = As_hi[(t + 4) * SPA + mbase + g];
        ah[3] = As_hi[(t + 4) * SPA + mbase + g + 8];
        al[0] = As_lo[t * SPA + mbase + g];
        al[1] = As_lo[t * SPA + mbase + g + 8];
        al[2] = As_lo[(t + 4) * SPA + mbase + g];
        al[3] = As_lo[(t + 4) * SPA + mbase + g + 8];
#pragma unroll
        for (int j = 0; j < 8; j++) {
            int n = nbase + j * 8 + g;
            unsigned bh0 = Wv_hi[t * SPW + n];
            unsigned bh1 = Wv_hi[(t + 4) * SPW + n];
            unsigned bl0 = Wv_lo[t * SPW + n];
            unsigned bl1 = Wv_lo[(t + 4) * SPW + n];
            asm volatile("mma.sync.aligned.m16n8k16.row.col.f32.bf16.bf16.f32 "
                         "{%0,%1,%2,%3}, {%4,%5,%6,%7}, {%8,%9}, {%0,%1,%2,%3};"
                         : "+f"(acc[j][0]), "+f"(acc[j][1]), "+f"(acc[j][2]), "+f"(acc[j][3])
                         : "r"(ah[0]), "r"(ah[1]), "r"(ah[2]), "r"(ah[3]), "r"(bh0), "r"(bh1));
            asm volatile("mma.sync.aligned.m16n8k16.row.col.f32.bf16.bf16.f32 "
                         "{%0,%1,%2,%3}, {%4,%5,%6,%7}, {%8,%9}, {%0,%1,%2,%3};"
                         : "+f"(acc[j][0]), "+f"(acc[j][1]), "+f"(acc[j][2]), "+f"(acc[j][3])
                         : "r"(ah[0]), "r"(ah[1]), "r"(ah[2]), "r"(ah[3]), "r"(bl0), "r"(bl1));
            asm volatile("mma.sync.aligned.m16n8k16.row.col.f32.bf16.bf16.f32 "
                         "{%0,%1,%2,%3}, {%4,%5,%6,%7}, {%8,%9}, {%0,%1,%2,%3};"
                         : "+f"(acc[j][0]), "+f"(acc[j][1]), "+f"(acc[j][2]), "+f"(acc[j][3])
                         : "r"(al[0]), "r"(al[1]), "r"(al[2]), "r"(al[3]), "r"(bh0), "r"(bh1));
        }
        __syncthreads();
    }

    int r0 = rowBase + mbase + g;
    int r1 = r0 + 8;
    if (r0 < N) {
#pragma unroll
        for (int j = 0; j < 8; j++)
            *reinterpret_cast<float2*>(&Cp[(size_t)r0 * HID + nbase + j * 8 + 2 * t]) =
                make_float2(acc[j][0], acc[j][1]);
    }
    if (r1 < N) {
#pragma unroll
        for (int j = 0; j < 8; j++)
            *reinterpret_cast<float2*>(&Cp[(size_t)r1 * HID + nbase + j * 8 + 2 * t]) =
                make_float2(acc[j][2], acc[j][3]);
    }
}

// ---------------- scatter: agg[col[e]] += m[row[e]] ----------------
__global__ void scatter_add(const float* __restrict__ m, const int* __restrict__ row,
                            const int* __restrict__ col, float* __restrict__ agg, int E) {
    int w = (blockIdx.x * blockDim.x + threadIdx.x) >> 5;
    if (w >= E) return;
    int lane = threadIdx.x & 31;
    int r = row[w];
    int c = col[w];
    float4 v = *reinterpret_cast<const float4*>(&m[(size_t)r * HID + lane * 4]);
    float* dst = &agg[(size_t)c * HID + lane * 4];
    asm volatile("red.global.add.v4.f32 [%0], {%1, %2, %3, %4};"
                 :: "l"(dst), "f"(v.x), "f"(v.y), "f"(v.z), "f"(v.w) : "memory");
}

// ---------------- fp16 mirror: aggh = (half)relu(agg) ----------------
__global__ void relu_fp16(const float4* __restrict__ agg4, uint2* __restrict__ aggh) {
    int i = blockIdx.x * blockDim.x + threadIdx.x;
    if (i >= NA4) return;
    float4 v = agg4[i];
    __half2 a = __float22half2_rn(make_float2(fmaxf(v.x, 0.f), fmaxf(v.y, 0.f)));
    __half2 b = __float22half2_rn(make_float2(fmaxf(v.z, 0.f), fmaxf(v.w, 0.f)));
    uint2 o;
    o.x = *reinterpret_cast<unsigned*>(&a);
    o.y = *reinterpret_cast<unsigned*>(&b);
    aggh[i] = o;
}

// ---------------- fused gamma over both edge lists, fp16 gathers ----------------
#define G2_CHUNK 64
__global__ void gamma_both(const uint2* __restrict__ aggh,
                           const int* __restrict__ row1, const int* __restrict__ col1,
                           float* __restrict__ s1, int E1, int blocks1,
                           const int* __restrict__ row2, const int* __restrict__ col2,
                           float* __restrict__ s2, int E2) {
    int lane = threadIdx.x & 31;
    if (blockIdx.x < blocks1) {
        int w = (blockIdx.x * blockDim.x + threadIdx.x) >> 5;
        if (w >= E1) return;
        int r = row1[w];
        int c = col1[w];
        float4 a = h4_to_f4(aggh[(size_t)r * 32 + lane]);
        float4 b = h4_to_f4(aggh[(size_t)c * 32 + lane]);
        float dx = a.x - b.x, dy = a.y - b.y, dz = a.z - b.z, dw = a.w - b.w;
        float s = warp_red(fmaf(dx, dx, fmaf(dy, dy, fmaf(dz, dz, dw * dw))));
        if (lane == 0) atomicAdd(&s1[r], s);
    } else {
        int w = (int)((((size_t)(blockIdx.x - blocks1) * blockDim.x) + threadIdx.x) >> 5);
        int base = w * G2_CHUNK;
        if (base >= E2) return;
        int end = min(base + G2_CHUNK, E2);
        int curR = row2[base];
        float4 ar = h4_to_f4(aggh[(size_t)curR * 32 + lane]);
        float acc = 0.0f;
        for (int e = base; e < end; e++) {
            int r = row2[e];
            if (r != curR) {
                float s = warp_red(acc);
                if (lane == 0) atomicAdd(&s2[curR], s);
                acc = 0.0f;
                curR = r;
                ar = h4_to_f4(aggh[(size_t)r * 32 + lane]);
            }
            int c = col2[e];
            float4 ac = h4_to_f4(aggh[(size_t)c * 32 + lane]);
            float dx = ar.x - ac.x, dy = ar.y - ac.y, dz = ar.z - ac.z, dw = ar.w - ac.w;
            acc += fmaf(dx, dx, fmaf(dy, dy, fmaf(dz, dz, dw * dw)));
        }
        float s = warp_red(acc);
        if (lane == 0) atomicAdd(&s2[curR], s);
    }
}

// ---------------- final GEMM with fused layer-2 h-update ----------------
#define ORPB 16
__global__ __launch_bounds__(640) void gemm_out_upd(
    const float* __restrict__ h, const float* __restrict__ agg, const float* __restrict__ skip,
    const float* __restrict__ s1, const float* __restrict__ s2,
    const float* __restrict__ deg1, const float* __restrict__ deg2,
    const float* __restrict__ W, const float* __restrict__ bias,
    float* __restrict__ C, int N) {
    __shared__ float Ws[HID * 41];
    __shared__ float bs[40];
    __shared__ float As[ORPB][HID];
    __shared__ float cg1[ORPB], cg2[ORPB], cid[ORPB];
    int tid = threadIdx.y * 40 + threadIdx.x;
    int rowBase = blockIdx.x * ORPB;

    for (int i = tid; i < HID * 40; i += 640) {
        int k = i / 40, n = i % 40;
        Ws[k * 41 + n] = W[i];
    }
    if (tid < 40) bs[tid] = bias[tid];
    if (tid < ORPB) {
        int r = rowBase + tid;
        float g1 = 0.f, g2 = 0.f, invd = 1.f;
        if (r < N) {
            g1 = tanhf(s1[r] / (deg1[r] + 1e-10f));
            g2 = tanhf(s2[r] / (deg2[r] + 1e-10f));
            invd = 1.0f / (1.0f + g1 + g2);
        }
        cg1[tid] = g1; cg2[tid] = g2; cid[tid] = invd;
    }
    __syncthreads();

    for (int i = tid; i < ORPB * HID; i += 640) {
        int rr = i >> 7, kk = i & (HID - 1);
        int r = rowBase + rr;
        float v = 0.0f;
        if (r < N) {
            size_t off = (size_t)r * HID + kk;
            v = (h[off] + cg1[rr] * fmaxf(agg[off], 0.f) + cg2[rr] * skip[off]) * cid[rr];
        }
        As[rr][kk] = v;
    }
    __syncthreads();

    int row = rowBase + threadIdx.y;
    if (row >= N) return;
    float acc = bs[threadIdx.x];
#pragma unroll
    for (int k = 0; k < HID; k++) acc = fmaf(As[threadIdx.y][k], Ws[k * 41 + threadIdx.x], acc);
    C[(size_t)row * 40 + threadIdx.x] = acc;
}

// ---------------- launcher ----------------
extern "C" void kernel_launch(void* const* d_in, const int* in_sizes, int n_in,
                              void* d_out, int out_size) {
    const float* x       = (const float*)d_in[0];
    const float* x0      = (const float*)d_in[1];
    const int*   ei      = (const int*)d_in[2];
    const int*   ei2     = (const int*)d_in[3];
    const float* in_W    = (const float*)d_in[4];
    const float* skip_W  = (const float*)d_in[5];
    const float* conv_W  = (const float*)d_in[6];
    const float* conv_b  = (const float*)d_in[7];
    const float* fc_W    = (const float*)d_in[8];
    const float* fc_b    = (const float*)d_in[9];
    float* out = (float*)d_out;

    const int E1 = in_sizes[2] / 2;
    const int E2 = in_sizes[3] / 2;
    const int* row1 = ei;
    const int* col1 = ei + E1;
    const int* row2 = ei2;
    const int* col2 = ei2 + E2;

    float* base;
    cudaGetSymbolAddress((void**)&base, g_scratch);
    float* h    = base + OFF_H;
    float* m    = base + OFF_M;
    float* skip = base + OFF_SKIP;
    float* agg0 = base + OFF_AGG0;
    float* s1a  = agg0 + NN * HID;
    float* s2a  = s1a + NN;
    float* agg1 = base + OFF_AGG1;
    float* s1b  = agg1 + NN * HID;
    float* s2b  = s1b + NN;
    float* deg1 = base + OFF_DEG;
    float* deg2 = deg1 + NN;
    uint2* aggh = (uint2*)(base + OFF_AGGH);
    float* wc1  = base + OFF_WC1;
    float* wc2  = base + OFF_WC2;
    unsigned* wpk = (unsigned*)(base + OFF_WPK);

    const int NTH = 256;
    const int zeroDegB = (2 * NN / 4 + NTH - 1) / NTH;
    const int cvtGrid  = (NA4 + NTH - 1) / NTH;
    const int blocks1  = (int)(((size_t)E1 * 32 + NTH - 1) / NTH);
    const int warps2   = (E2 + G2_CHUNK - 1) / G2_CHUNK;
    const int blocks2  = (warps2 * 32 + NTH - 1) / NTH;
    const int scatB    = (int)(((size_t)E1 * 32 + NTH - 1) / NTH);
    const int countB   = (E1 + E2 + NTH - 1) / NTH;

    // pre1: Wc1/Wc2 tiny GEMMs + zero degrees
    pre1<<<16 + zeroDegB, NTH>>>(in_W, skip_W, conv_W, wc1, wc2, (float4*)deg1);
    // pre2: weight prepack (mats 0..3) + degree count
    pre2<<<128 + countB, NTH>>>(in_W, wc1, wc2, conv_W + (size_t)HID * HID, wpk,
                                row1, E1, row2, E2, deg1);

    // triple GEMM (h = x@in_W ; skip = x0@Wc1 ; m = x@Wc2) + init agg0|s1a|s2a
    gemm_k<3><<<3 * GBM + INITB, NTH>>>(x, x0, wpk, h, skip, m,
                                        nullptr, nullptr, nullptr, nullptr, nullptr, nullptr,
                                        nullptr,
                                        (float4*)agg0, (const float4*)conv_b, 3 * GBM, NN);

    // ---- layer 0 ----
    scatter_add<<<scatB, NTH>>>(m, row1, col1, agg0, E1);
    relu_fp16<<<cvtGrid, NTH>>>((const float4*)agg0, aggh);
    gamma_both<<<blocks1 + blocks2, NTH>>>(aggh, row1, col1, s1a, E1, blocks1,
                                           row2, col2, s2a, E2);

    // ---- layer 1: conv GEMM with fused h-update + init agg1|s1b|s2b ----
    gemm_k<2><<<GBM + INITB, NTH>>>(h, nullptr, wpk, m, nullptr, nullptr,
                                    agg0, skip, s1a, s2a, deg1, deg2, h,
                                    (float4*)agg1, (const float4*)(conv_b + HID), GBM, NN);
    scatter_add<<<scatB, NTH>>>(m, row1, col1, agg1, E1);
    relu_fp16<<<cvtGrid, NTH>>>((const float4*)agg1, aggh);
    gamma_both<<<blocks1 + blocks2, NTH>>>(aggh, row1, col1, s1b, E1, blocks1,
                                           row2, col2, s2b, E2);

    // ---- output (layer-2 h-update fused) ----
    gemm_out_upd<<<(NN + ORPB - 1) / ORPB, dim3(40, ORPB)>>>(
        h, agg1, skip, s1b, s2b, deg1, deg2, fc_W, fc_b, out, NN);
}